// round 1
// baseline (speedup 1.0000x reference)
#include <cuda_runtime.h>
#include <cstdint>

#define D_IN   2048
#define D_OUT  2048
#define RANK   16
#define LSCALE 2.0f      // 32.0 / 16.0

#define BM  128
#define BN  128
#define BK  32
#define BKP 36           // padded row stride (floats) -> conflict-free LDS, keeps 16B align
#define KT  (D_IN / BK)  // 64 k-tiles

#define SMEM_BYTES (4 * BM * BKP * 4)   // 2 stages A + 2 stages B = 73728 B

#define MAX_M 8192
__device__ float g_low[MAX_M * RANK];   // scratch for x @ lora_A^T

// ---------------------------------------------------------------------------
// helpers
// ---------------------------------------------------------------------------
__device__ __forceinline__ uint32_t f2tf32(float f) {
    uint32_t u;
    asm volatile("cvt.rna.tf32.f32 %0, %1;" : "=r"(u) : "f"(f));
    return u;
}

__device__ __forceinline__ void cpasync16(uint32_t saddr, const void* gptr) {
    asm volatile("cp.async.cg.shared.global [%0], [%1], 16;" :: "r"(saddr), "l"(gptr));
}

// ---------------------------------------------------------------------------
// Kernel 1: low[m, r] = sum_k x[m,k] * lora_A[r,k]   (fp32 exact)
// one warp per m-row; lane covers k with float4 strides
// ---------------------------------------------------------------------------
__global__ __launch_bounds__(256)
void lora_low_kernel(const float* __restrict__ x, const float* __restrict__ lA,
                     int M) {
    int warp_id = (blockIdx.x * blockDim.x + threadIdx.x) >> 5;
    int lane    = threadIdx.x & 31;
    if (warp_id >= M) return;

    const float* xr = x + (size_t)warp_id * D_IN;
    float acc[RANK];
#pragma unroll
    for (int r = 0; r < RANK; r++) acc[r] = 0.0f;

#pragma unroll 4
    for (int it = 0; it < D_IN / 128; it++) {       // 16 iters
        int k = it * 128 + lane * 4;
        float4 xv = *reinterpret_cast<const float4*>(xr + k);
#pragma unroll
        for (int r = 0; r < RANK; r++) {
            float4 av = *reinterpret_cast<const float4*>(lA + (size_t)r * D_IN + k);
            acc[r] += xv.x * av.x + xv.y * av.y + xv.z * av.z + xv.w * av.w;
        }
    }

#pragma unroll
    for (int off = 16; off; off >>= 1)
#pragma unroll
        for (int r = 0; r < RANK; r++)
            acc[r] += __shfl_xor_sync(0xffffffffu, acc[r], off);

    if (lane == 0) {
        float* lrow = g_low + (size_t)warp_id * RANK;
#pragma unroll
        for (int r = 0; r < RANK; r++) lrow[r] = acc[r];
    }
}

// ---------------------------------------------------------------------------
// Kernel 2: out = x @ W^T + b + (low @ (scale*lora_B)^T)
// 128x128x32 tiles, double-buffered cp.async, mma.sync m16n8k8 tf32
// 8 warps: warp tile 64(m) x 32(n) = 4x4 mma tiles
// ---------------------------------------------------------------------------
template <int NSTEPS>
__device__ __forceinline__ void mma_steps(const float* __restrict__ At,
                                          const float* __restrict__ Bt,
                                          int wm, int wn, int g, int tg,
                                          float c[4][4][4]) {
#pragma unroll
    for (int ks = 0; ks < NSTEPS; ks++) {
        const int k0 = ks * 8;
        uint32_t bf[4][2];
#pragma unroll
        for (int j = 0; j < 4; j++) {
            const float* bp = Bt + (wn * 32 + j * 8 + g) * BKP + k0 + tg;
            bf[j][0] = f2tf32(bp[0]);
            bf[j][1] = f2tf32(bp[4]);
        }
#pragma unroll
        for (int i = 0; i < 4; i++) {
            const float* ap = At + (wm * 64 + i * 16 + g) * BKP + k0 + tg;
            uint32_t a0 = f2tf32(ap[0]);
            uint32_t a1 = f2tf32(ap[8 * BKP]);
            uint32_t a2 = f2tf32(ap[4]);
            uint32_t a3 = f2tf32(ap[8 * BKP + 4]);
#pragma unroll
            for (int j = 0; j < 4; j++) {
                asm volatile(
                    "mma.sync.aligned.m16n8k8.row.col.f32.tf32.tf32.f32 "
                    "{%0,%1,%2,%3}, {%4,%5,%6,%7}, {%8,%9}, {%0,%1,%2,%3};"
                    : "+f"(c[i][j][0]), "+f"(c[i][j][1]),
                      "+f"(c[i][j][2]), "+f"(c[i][j][3])
                    : "r"(a0), "r"(a1), "r"(a2), "r"(a3),
                      "r"(bf[j][0]), "r"(bf[j][1]));
            }
        }
    }
}

__device__ __forceinline__ void load_stage(uint32_t s_as, uint32_t s_bs,
                                           const float* __restrict__ xA,
                                           const float* __restrict__ wB,
                                           int kt, int tid) {
#pragma unroll
    for (int i = 0; i < 4; i++) {
        int idx = tid + i * 256;     // 0..1023
        int row = idx >> 3;          // 0..127
        int cg  = idx & 7;           // col group of 4 floats
        cpasync16(s_as + (row * BKP + cg * 4) * 4,
                  xA + (size_t)row * D_IN + kt + cg * 4);
        cpasync16(s_bs + (row * BKP + cg * 4) * 4,
                  wB + (size_t)row * D_IN + kt + cg * 4);
    }
}

__global__ __launch_bounds__(256, 2)
void gemm_lora_kernel(const float* __restrict__ x, const float* __restrict__ W,
                      const float* __restrict__ bias,
                      const float* __restrict__ lB,
                      float* __restrict__ out, int M) {
    extern __shared__ float smem[];
    float* As0 = smem;
    float* As1 = smem + BM * BKP;
    float* Bs0 = smem + 2 * BM * BKP;
    float* Bs1 = smem + 3 * BM * BKP;

    const int tid  = threadIdx.x;
    const int lane = tid & 31;
    const int warp = tid >> 5;
    const int wm   = warp >> 2;   // 0..1
    const int wn   = warp & 3;    // 0..3
    const int g    = lane >> 2;   // group id 0..7
    const int tg   = lane & 3;    // thread-in-group 0..3
    const int m0   = blockIdx.y * BM;
    const int n0   = blockIdx.x * BN;

    const uint32_t sbase = (uint32_t)__cvta_generic_to_shared(smem);
    const uint32_t sA[2] = { sbase, sbase + BM * BKP * 4 };
    const uint32_t sB[2] = { sbase + 2 * BM * BKP * 4, sbase + 3 * BM * BKP * 4 };

    const float* xA = x + (size_t)m0 * D_IN;
    const float* wB = W + (size_t)n0 * D_IN;

    float c[4][4][4];
#pragma unroll
    for (int i = 0; i < 4; i++)
#pragma unroll
        for (int j = 0; j < 4; j++)
#pragma unroll
            for (int q = 0; q < 4; q++) c[i][j][q] = 0.0f;

    // prologue: stage 0
    load_stage(sA[0], sB[0], xA, wB, 0, tid);
    asm volatile("cp.async.commit_group;");

    for (int t = 0; t < KT; t++) {
        const int cur = t & 1;
        if (t + 1 < KT) {
            load_stage(sA[cur ^ 1], sB[cur ^ 1], xA, wB, (t + 1) * BK, tid);
            asm volatile("cp.async.commit_group;");
            asm volatile("cp.async.wait_group 1;");
        } else {
            asm volatile("cp.async.wait_group 0;");
        }
        __syncthreads();
        mma_steps<4>(cur ? As1 : As0, cur ? Bs1 : Bs0, wm, wn, g, tg, c);
        __syncthreads();
    }

    // ---- LoRA fold: two extra k-steps with A<-low tile, B<-scale*lora_B tile
#pragma unroll
    for (int i = 0; i < 2; i++) {
        int idx = tid + i * 256;    // 0..511
        int row = idx >> 2;         // 0..127
        int cg  = idx & 3;          // 0..3 -> cols cg*4..cg*4+3
        float4 lv = *reinterpret_cast<const float4*>(
            g_low + (size_t)(m0 + row) * RANK + cg * 4);
        *reinterpret_cast<float4*>(As0 + row * BKP + cg * 4) = lv;
        float4 bv = *reinterpret_cast<const float4*>(
            lB + (size_t)(n0 + row) * RANK + cg * 4);
        bv.x *= LSCALE; bv.y *= LSCALE; bv.z *= LSCALE; bv.w *= LSCALE;
        *reinterpret_cast<float4*>(Bs0 + row * BKP + cg * 4) = bv;
    }
    __syncthreads();
    mma_steps<2>(As0, Bs0, wm, wn, g, tg, c);   // rank 16 = 2 x (k=8)

    // ---- epilogue: add bias, store float2 pairs
#pragma unroll
    for (int i = 0; i < 4; i++) {
        int m = m0 + wm * 64 + i * 16 + g;
        float* orow0 = out + (size_t)m * D_OUT;
        float* orow1 = orow0 + (size_t)8 * D_OUT;
#pragma unroll
        for (int j = 0; j < 4; j++) {
            int n = n0 + wn * 32 + j * 8 + 2 * tg;
            float b0 = bias[n];
            float b1 = bias[n + 1];
            float2 v0 = make_float2(c[i][j][0] + b0, c[i][j][1] + b1);
            float2 v1 = make_float2(c[i][j][2] + b0, c[i][j][3] + b1);
            *reinterpret_cast<float2*>(orow0 + n) = v0;
            *reinterpret_cast<float2*>(orow1 + n) = v1;
        }
    }
}

// ---------------------------------------------------------------------------
// launch
// ---------------------------------------------------------------------------
extern "C" void kernel_launch(void* const* d_in, const int* in_sizes, int n_in,
                              void* d_out, int out_size) {
    const float* x  = (const float*)d_in[0];
    const float* W  = (const float*)d_in[1];
    const float* b  = (const float*)d_in[2];
    const float* lA = (const float*)d_in[3];
    const float* lB = (const float*)d_in[4];
    float* out = (float*)d_out;

    const int M = in_sizes[0] / D_IN;   // 8192

    // low = x @ lora_A^T
    lora_low_kernel<<<(M + 7) / 8, 256>>>(x, lA, M);

    cudaFuncSetAttribute(gemm_lora_kernel,
                         cudaFuncAttributeMaxDynamicSharedMemorySize, SMEM_BYTES);
    dim3 grid(D_OUT / BN, M / BM);      // (16, 64)
    gemm_lora_kernel<<<grid, 256, SMEM_BYTES>>>(x, W, b, lB, out, M);
}

// round 3
// speedup vs baseline: 1.1148x; 1.1148x over previous
#include <cuda_runtime.h>
#include <cstdint>

#define D_IN   2048
#define D_OUT  2048
#define RANK   16
#define LSCALE 2.0f

#define BM  128
#define BN  128
#define BK  32
#define BKP 36            // padded row stride (floats): 144B rows, 16B-aligned, conflict-free
#define KT  (D_IN / BK)   // 64 main k-tiles
#define NT  (KT + 1)      // +1 LoRA tile (rank 16 = 2 k-steps)
#define NSTAGE 3

#define TILE_FLOATS (BM * BKP)                       // per A or B half: 4608 floats
#define STG_FLOATS  (2 * TILE_FLOATS)
#define SMEM_BYTES  (NSTAGE * STG_FLOATS * 4)        // 110592 B

__device__ float g_low[8192 * RANK];   // LSCALE pre-applied in kernel 1

// ---------------------------------------------------------------- helpers
__device__ __forceinline__ void cpasync16(uint32_t saddr, const void* gptr) {
    asm volatile("cp.async.cg.shared.global [%0], [%1], 16;" :: "r"(saddr), "l"(gptr));
}

// ---------------------------------------------------------------------------
// Kernel 1: g_low[m, r] = LSCALE * sum_k x[m,k] * lora_A[r,k]
// 4 rows per warp: each lora_A fragment reused across 4 x-rows
// ---------------------------------------------------------------------------
__global__ __launch_bounds__(256)
void lora_low_kernel(const float* __restrict__ x, const float* __restrict__ lA) {
    int gw   = (blockIdx.x * blockDim.x + threadIdx.x) >> 5;
    int lane = threadIdx.x & 31;
    int mb   = gw * 4;

    const float* xr = x + (size_t)mb * D_IN;
    float acc[4][RANK];
#pragma unroll
    for (int q = 0; q < 4; q++)
#pragma unroll
        for (int r = 0; r < RANK; r++) acc[q][r] = 0.0f;

    for (int it = 0; it < D_IN / 128; it++) {
        int k = it * 128 + lane * 4;
        float4 xv[4];
#pragma unroll
        for (int q = 0; q < 4; q++)
            xv[q] = *reinterpret_cast<const float4*>(xr + (size_t)q * D_IN + k);
#pragma unroll
        for (int r = 0; r < RANK; r++) {
            float4 av = *reinterpret_cast<const float4*>(lA + (size_t)r * D_IN + k);
#pragma unroll
            for (int q = 0; q < 4; q++)
                acc[q][r] += xv[q].x * av.x + xv[q].y * av.y + xv[q].z * av.z + xv[q].w * av.w;
        }
    }

#pragma unroll
    for (int off = 16; off; off >>= 1)
#pragma unroll
        for (int q = 0; q < 4; q++)
#pragma unroll
            for (int r = 0; r < RANK; r++)
                acc[q][r] += __shfl_xor_sync(0xffffffffu, acc[q][r], off);

    if (lane == 0) {
#pragma unroll
        for (int q = 0; q < 4; q++) {
            float* dst = g_low + (size_t)(mb + q) * RANK;
#pragma unroll
            for (int j = 0; j < 4; j++) {
                float4 v = make_float4(acc[q][j * 4 + 0] * LSCALE, acc[q][j * 4 + 1] * LSCALE,
                                       acc[q][j * 4 + 2] * LSCALE, acc[q][j * 4 + 3] * LSCALE);
                *reinterpret_cast<float4*>(dst + j * 4) = v;
            }
        }
    }
}

// ---------------------------------------------------------------------------
// Kernel 2: out = x @ W^T + b + low @ (scale*lora_B)^T
// 128x128x32 tiles, 3-stage cp.async, mma.sync m16n8k8 tf32 (raw fp32 bits,
// no cvt). 8 warps, warp tile 64x32 (4x4 mma tiles), 1 syncthreads / k-tile.
// ---------------------------------------------------------------------------
template <int NSTEPS>
__device__ __forceinline__ void mma_steps(const float* __restrict__ At,
                                          const float* __restrict__ Bt,
                                          int wm, int wn, int g, int tg,
                                          float c[4][4][4]) {
#pragma unroll
    for (int ks = 0; ks < NSTEPS; ks++) {
        const int k0 = ks * 8;
        uint32_t bf[4][2];
#pragma unroll
        for (int j = 0; j < 4; j++) {
            const float* bp = Bt + (wn * 32 + j * 8 + g) * BKP + k0 + tg;
            bf[j][0] = __float_as_uint(bp[0]);      // raw fp32 bits as tf32
            bf[j][1] = __float_as_uint(bp[4]);
        }
#pragma unroll
        for (int i = 0; i < 4; i++) {
            const float* ap = At + (wm * 64 + i * 16 + g) * BKP + k0 + tg;
            uint32_t a0 = __float_as_uint(ap[0]);
            uint32_t a1 = __float_as_uint(ap[8 * BKP]);
            uint32_t a2 = __float_as_uint(ap[4]);
            uint32_t a3 = __float_as_uint(ap[8 * BKP + 4]);
#pragma unroll
            for (int j = 0; j < 4; j++) {
                asm volatile(
                    "mma.sync.aligned.m16n8k8.row.col.f32.tf32.tf32.f32 "
                    "{%0,%1,%2,%3}, {%4,%5,%6,%7}, {%8,%9}, {%0,%1,%2,%3};"
                    : "+f"(c[i][j][0]), "+f"(c[i][j][1]),
                      "+f"(c[i][j][2]), "+f"(c[i][j][3])
                    : "r"(a0), "r"(a1), "r"(a2), "r"(a3),
                      "r"(bf[j][0]), "r"(bf[j][1]));
            }
        }
    }
}

__device__ __forceinline__ void load_tile(float* stage,
                                          const float* __restrict__ xA,
                                          const float* __restrict__ wB,
                                          const float* __restrict__ lB,
                                          int m0, int n0, int t, int tid) {
    uint32_t sa = (uint32_t)__cvta_generic_to_shared(stage);
    uint32_t sb = sa + TILE_FLOATS * 4;
    if (t < KT) {
        const int k0 = t * BK;
#pragma unroll
        for (int i = 0; i < 4; i++) {
            int idx = tid + i * 256;     // 0..1023
            int row = idx >> 3;          // 0..127
            int cg  = idx & 7;           // 4-float group
            cpasync16(sa + (row * BKP + cg * 4) * 4, xA + (size_t)row * D_IN + k0 + cg * 4);
            cpasync16(sb + (row * BKP + cg * 4) * 4, wB + (size_t)row * D_IN + k0 + cg * 4);
        }
    } else {
        // LoRA tile: A <- g_low[m0+row, 0..15], B <- lora_B[n0+row, 0..15]
#pragma unroll
        for (int i = 0; i < 2; i++) {
            int idx = tid + i * 256;     // 0..511
            int row = idx >> 2;          // 0..127
            int cg  = idx & 3;           // 0..3
            cpasync16(sa + (row * BKP + cg * 4) * 4, g_low + (size_t)(m0 + row) * RANK + cg * 4);
            cpasync16(sb + (row * BKP + cg * 4) * 4, lB + (size_t)(n0 + row) * RANK + cg * 4);
        }
    }
}

__global__ __launch_bounds__(256, 2)
void gemm_lora_kernel(const float* __restrict__ x, const float* __restrict__ W,
                      const float* __restrict__ bias,
                      const float* __restrict__ lB,
                      float* __restrict__ out) {
    extern __shared__ float smem[];

    const int tid  = threadIdx.x;
    const int lane = tid & 31;
    const int warp = tid >> 5;
    const int wm   = warp >> 2;   // 0..1
    const int wn   = warp & 3;    // 0..3
    const int g    = lane >> 2;
    const int tg   = lane & 3;
    const int m0   = blockIdx.y * BM;
    const int n0   = blockIdx.x * BN;

    const float* xA = x + (size_t)m0 * D_IN;
    const float* wB = W + (size_t)n0 * D_IN;

    float c[4][4][4];
#pragma unroll
    for (int i = 0; i < 4; i++)
#pragma unroll
        for (int j = 0; j < 4; j++)
#pragma unroll
            for (int q = 0; q < 4; q++) c[i][j][q] = 0.0f;

    // prologue: tiles 0 and 1
    load_tile(smem + 0 * STG_FLOATS, xA, wB, lB, m0, n0, 0, tid);
    asm volatile("cp.async.commit_group;");
    load_tile(smem + 1 * STG_FLOATS, xA, wB, lB, m0, n0, 1, tid);
    asm volatile("cp.async.commit_group;");

    int buf = 0;
    for (int t = 0; t < NT; t++) {
        asm volatile("cp.async.wait_group 1;");   // tile t resident
        __syncthreads();                          // all warps done with buf (t-1)%3 too

        // prefetch tile t+2 into the buffer freed at t-1
        if (t + 2 < NT) {
            int nb = buf + 2; if (nb >= NSTAGE) nb -= NSTAGE;
            load_tile(smem + nb * STG_FLOATS, xA, wB, lB, m0, n0, t + 2, tid);
        }
        asm volatile("cp.async.commit_group;");   // (empty group near the tail is fine)

        const float* At = smem + buf * STG_FLOATS;
        const float* Bt = At + TILE_FLOATS;
        if (t < KT) mma_steps<4>(At, Bt, wm, wn, g, tg, c);
        else        mma_steps<2>(At, Bt, wm, wn, g, tg, c);   // rank 16 = 2 k-steps

        if (++buf == NSTAGE) buf = 0;
    }

    // epilogue: add bias, store float2 pairs
#pragma unroll
    for (int i = 0; i < 4; i++) {
        int m = m0 + wm * 64 + i * 16 + g;
        float* orow0 = out + (size_t)m * D_OUT;
        float* orow1 = orow0 + (size_t)8 * D_OUT;
#pragma unroll
        for (int j = 0; j < 4; j++) {
            int n = n0 + wn * 32 + j * 8 + 2 * tg;
            float b0 = bias[n];
            float b1 = bias[n + 1];
            *reinterpret_cast<float2*>(orow0 + n) =
                make_float2(c[i][j][0] + b0, c[i][j][1] + b1);
            *reinterpret_cast<float2*>(orow1 + n) =
                make_float2(c[i][j][2] + b0, c[i][j][3] + b1);
        }
    }
}

// ---------------------------------------------------------------------------
extern "C" void kernel_launch(void* const* d_in, const int* in_sizes, int n_in,
                              void* d_out, int out_size) {
    const float* x  = (const float*)d_in[0];
    const float* W  = (const float*)d_in[1];
    const float* b  = (const float*)d_in[2];
    const float* lA = (const float*)d_in[3];
    const float* lB = (const float*)d_in[4];
    float* out = (float*)d_out;

    const int M = in_sizes[0] / D_IN;   // 8192

    lora_low_kernel<<<M / 32, 256>>>(x, lA);

    cudaFuncSetAttribute(gemm_lora_kernel,
                         cudaFuncAttributeMaxDynamicSharedMemorySize, SMEM_BYTES);
    dim3 grid(D_OUT / BN, M / BM);      // (16, 64)
    gemm_lora_kernel<<<grid, 256, SMEM_BYTES>>>(x, W, b, lB, out);
}

// round 4
// speedup vs baseline: 1.1253x; 1.0094x over previous
#include <cuda_runtime.h>
#include <cstdint>

#define D_IN   2048
#define D_OUT  2048
#define RANK   16
#define LSCALE 2.0f

#define BM  128
#define BN  128
#define BK  32
#define BKP 36            // padded row stride (floats): conflict-free, 16B-aligned
#define KT  (D_IN / BK)   // 64 main k-tiles
#define NT  (KT + 1)      // +1 LoRA tile (rank 16 = 2 k-steps)
#define NSTAGE 3

#define TILE_FLOATS (BM * BKP)
#define STG_FLOATS  (2 * TILE_FLOATS)
#define SMEM_BYTES  (NSTAGE * STG_FLOATS * 4)   // 110592 B -> 2 CTAs/SM

__device__ float g_low[8192 * RANK];   // LSCALE pre-applied in kernel 1

// ---------------------------------------------------------------- helpers
__device__ __forceinline__ void cpasync16(uint32_t saddr, const void* gptr) {
    asm volatile("cp.async.cg.shared.global [%0], [%1], 16;" :: "r"(saddr), "l"(gptr));
}

__device__ __forceinline__ void mma_tf32(float c[4], uint32_t a0, uint32_t a1,
                                         uint32_t a2, uint32_t a3,
                                         uint32_t b0, uint32_t b1) {
    asm volatile(
        "mma.sync.aligned.m16n8k8.row.col.f32.tf32.tf32.f32 "
        "{%0,%1,%2,%3}, {%4,%5,%6,%7}, {%8,%9}, {%0,%1,%2,%3};"
        : "+f"(c[0]), "+f"(c[1]), "+f"(c[2]), "+f"(c[3])
        : "r"(a0), "r"(a1), "r"(a2), "r"(a3), "r"(b0), "r"(b1));
}

// ---------------------------------------------------------------------------
// Kernel 1: g_low[m, r] = LSCALE * sum_k x[m,k] * lora_A[r,k]
// ---------------------------------------------------------------------------
__global__ __launch_bounds__(256)
void lora_low_kernel(const float* __restrict__ x, const float* __restrict__ lA) {
    int gw   = (blockIdx.x * blockDim.x + threadIdx.x) >> 5;
    int lane = threadIdx.x & 31;
    int mb   = gw * 4;

    const float* xr = x + (size_t)mb * D_IN;
    float acc[4][RANK];
#pragma unroll
    for (int q = 0; q < 4; q++)
#pragma unroll
        for (int r = 0; r < RANK; r++) acc[q][r] = 0.0f;

    for (int it = 0; it < D_IN / 128; it++) {
        int k = it * 128 + lane * 4;
        float4 xv[4];
#pragma unroll
        for (int q = 0; q < 4; q++)
            xv[q] = *reinterpret_cast<const float4*>(xr + (size_t)q * D_IN + k);
#pragma unroll
        for (int r = 0; r < RANK; r++) {
            float4 av = *reinterpret_cast<const float4*>(lA + (size_t)r * D_IN + k);
#pragma unroll
            for (int q = 0; q < 4; q++)
                acc[q][r] += xv[q].x * av.x + xv[q].y * av.y + xv[q].z * av.z + xv[q].w * av.w;
        }
    }

#pragma unroll
    for (int off = 16; off; off >>= 1)
#pragma unroll
        for (int q = 0; q < 4; q++)
#pragma unroll
            for (int r = 0; r < RANK; r++)
                acc[q][r] += __shfl_xor_sync(0xffffffffu, acc[q][r], off);

    if (lane == 0) {
#pragma unroll
        for (int q = 0; q < 4; q++) {
            float* dst = g_low + (size_t)(mb + q) * RANK;
#pragma unroll
            for (int j = 0; j < 4; j++) {
                float4 v = make_float4(acc[q][j * 4 + 0] * LSCALE, acc[q][j * 4 + 1] * LSCALE,
                                       acc[q][j * 4 + 2] * LSCALE, acc[q][j * 4 + 3] * LSCALE);
                *reinterpret_cast<float4*>(dst + j * 4) = v;
            }
        }
    }
}

// ---------------------------------------------------------------------------
// Kernel 2 mainloop: B frags hoisted per tile, A frags software-pipelined
// ---------------------------------------------------------------------------
__device__ __forceinline__ void lda_frag(uint32_t f[4], const float* Abase,
                                         int ks, int i) {
    const float* ap = Abase + i * 16 * BKP + ks * 8;
    f[0] = __float_as_uint(ap[0]);
    f[1] = __float_as_uint(ap[8 * BKP]);
    f[2] = __float_as_uint(ap[4]);
    f[3] = __float_as_uint(ap[8 * BKP + 4]);
}

__device__ __forceinline__ void mma_tile4(const float* __restrict__ At,
                                          const float* __restrict__ Bt,
                                          int wm, int wn, int g, int tg,
                                          float c[4][4][4]) {
    // hoist all B fragments for the tile: 4 ks x 4 j x 2 regs = 32 regs
    uint32_t bf[4][4][2];
#pragma unroll
    for (int ks = 0; ks < 4; ks++)
#pragma unroll
        for (int j = 0; j < 4; j++) {
            const float* bp = Bt + (wn * 32 + j * 8 + g) * BKP + ks * 8 + tg;
            bf[ks][j][0] = __float_as_uint(bp[0]);
            bf[ks][j][1] = __float_as_uint(bp[4]);
        }

    const float* Abase = At + (wm * 64 + g) * BKP + tg;
    uint32_t af[2][4];
    lda_frag(af[0], Abase, 0, 0);

#pragma unroll
    for (int ks = 0; ks < 4; ks++)
#pragma unroll
        for (int i = 0; i < 4; i++) {
            const int idx = ks * 4 + i;
            const int cb = idx & 1, nb = cb ^ 1;
            if (idx + 1 < 16)
                lda_frag(af[nb], Abase, (idx + 1) >> 2, (idx + 1) & 3);
#pragma unroll
            for (int j = 0; j < 4; j++)
                mma_tf32(c[i][j], af[cb][0], af[cb][1], af[cb][2], af[cb][3],
                         bf[ks][j][0], bf[ks][j][1]);
        }
}

// LoRA tile: only 2 k-steps, cold path, simple version
__device__ __forceinline__ void mma_tile2(const float* __restrict__ At,
                                          const float* __restrict__ Bt,
                                          int wm, int wn, int g, int tg,
                                          float c[4][4][4]) {
#pragma unroll
    for (int ks = 0; ks < 2; ks++) {
        const int k0 = ks * 8;
        uint32_t bf[4][2];
#pragma unroll
        for (int j = 0; j < 4; j++) {
            const float* bp = Bt + (wn * 32 + j * 8 + g) * BKP + k0 + tg;
            bf[j][0] = __float_as_uint(bp[0]);
            bf[j][1] = __float_as_uint(bp[4]);
        }
#pragma unroll
        for (int i = 0; i < 4; i++) {
            const float* ap = At + (wm * 64 + i * 16 + g) * BKP + k0 + tg;
            uint32_t a0 = __float_as_uint(ap[0]);
            uint32_t a1 = __float_as_uint(ap[8 * BKP]);
            uint32_t a2 = __float_as_uint(ap[4]);
            uint32_t a3 = __float_as_uint(ap[8 * BKP + 4]);
#pragma unroll
            for (int j = 0; j < 4; j++)
                mma_tf32(c[i][j], a0, a1, a2, a3, bf[j][0], bf[j][1]);
        }
    }
}

__device__ __forceinline__ void load_tile(float* stage,
                                          const float* __restrict__ xA,
                                          const float* __restrict__ wB,
                                          const float* __restrict__ lB,
                                          int m0, int n0, int t, int tid) {
    uint32_t sa = (uint32_t)__cvta_generic_to_shared(stage);
    uint32_t sb = sa + TILE_FLOATS * 4;
    if (t < KT) {
        const int k0 = t * BK;
#pragma unroll
        for (int i = 0; i < 4; i++) {
            int idx = tid + i * 256;
            int row = idx >> 3;
            int cg  = idx & 7;
            cpasync16(sa + (row * BKP + cg * 4) * 4, xA + (size_t)row * D_IN + k0 + cg * 4);
            cpasync16(sb + (row * BKP + cg * 4) * 4, wB + (size_t)row * D_IN + k0 + cg * 4);
        }
    } else {
#pragma unroll
        for (int i = 0; i < 2; i++) {
            int idx = tid + i * 256;
            int row = idx >> 2;
            int cg  = idx & 3;
            cpasync16(sa + (row * BKP + cg * 4) * 4, g_low + (size_t)(m0 + row) * RANK + cg * 4);
            cpasync16(sb + (row * BKP + cg * 4) * 4, lB + (size_t)(n0 + row) * RANK + cg * 4);
        }
    }
}

__global__ __launch_bounds__(256, 2)
void gemm_lora_kernel(const float* __restrict__ x, const float* __restrict__ W,
                      const float* __restrict__ bias,
                      const float* __restrict__ lB,
                      float* __restrict__ out) {
    extern __shared__ float smem[];

    const int tid  = threadIdx.x;
    const int lane = tid & 31;
    const int warp = tid >> 5;
    const int wm   = warp >> 2;
    const int wn   = warp & 3;
    const int g    = lane >> 2;
    const int tg   = lane & 3;
    const int m0   = blockIdx.y * BM;
    const int n0   = blockIdx.x * BN;

    const float* xA = x + (size_t)m0 * D_IN;
    const float* wB = W + (size_t)n0 * D_IN;

    float c[4][4][4];
#pragma unroll
    for (int i = 0; i < 4; i++)
#pragma unroll
        for (int j = 0; j < 4; j++)
#pragma unroll
            for (int q = 0; q < 4; q++) c[i][j][q] = 0.0f;

    load_tile(smem + 0 * STG_FLOATS, xA, wB, lB, m0, n0, 0, tid);
    asm volatile("cp.async.commit_group;");
    load_tile(smem + 1 * STG_FLOATS, xA, wB, lB, m0, n0, 1, tid);
    asm volatile("cp.async.commit_group;");

    int buf = 0;
    for (int t = 0; t < NT; t++) {
        asm volatile("cp.async.wait_group 1;");
        __syncthreads();

        if (t + 2 < NT) {
            int nb = buf + 2; if (nb >= NSTAGE) nb -= NSTAGE;
            load_tile(smem + nb * STG_FLOATS, xA, wB, lB, m0, n0, t + 2, tid);
        }
        asm volatile("cp.async.commit_group;");

        const float* At = smem + buf * STG_FLOATS;
        const float* Bt = At + TILE_FLOATS;
        if (t < KT) mma_tile4(At, Bt, wm, wn, g, tg, c);
        else        mma_tile2(At, Bt, wm, wn, g, tg, c);

        if (++buf == NSTAGE) buf = 0;
    }

    // epilogue: add bias, store float2 pairs
#pragma unroll
    for (int i = 0; i < 4; i++) {
        int m = m0 + wm * 64 + i * 16 + g;
        float* orow0 = out + (size_t)m * D_OUT;
        float* orow1 = orow0 + (size_t)8 * D_OUT;
#pragma unroll
        for (int j = 0; j < 4; j++) {
            int n = n0 + wn * 32 + j * 8 + 2 * tg;
            float b0 = bias[n];
            float b1 = bias[n + 1];
            *reinterpret_cast<float2*>(orow0 + n) =
                make_float2(c[i][j][0] + b0, c[i][j][1] + b1);
            *reinterpret_cast<float2*>(orow1 + n) =
                make_float2(c[i][j][2] + b0, c[i][j][3] + b1);
        }
    }
}

// ---------------------------------------------------------------------------
extern "C" void kernel_launch(void* const* d_in, const int* in_sizes, int n_in,
                              void* d_out, int out_size) {
    const float* x  = (const float*)d_in[0];
    const float* W  = (const float*)d_in[1];
    const float* b  = (const float*)d_in[2];
    const float* lA = (const float*)d_in[3];
    const float* lB = (const float*)d_in[4];
    float* out = (float*)d_out;

    const int M = in_sizes[0] / D_IN;   // 8192

    lora_low_kernel<<<M / 32, 256>>>(x, lA);

    cudaFuncSetAttribute(gemm_lora_kernel,
                         cudaFuncAttributeMaxDynamicSharedMemorySize, SMEM_BYTES);
    dim3 grid(D_OUT / BN, M / BM);      // (16, 64)
    gemm_lora_kernel<<<grid, 256, SMEM_BYTES>>>(x, W, b, lB, out);
}

// round 5
// speedup vs baseline: 1.4065x; 1.2499x over previous
#include <cuda_runtime.h>
#include <cstdint>

#define D_IN   2048
#define D_OUT  2048
#define RANK   16
#define LSCALE 2.0f

#define BM  128
#define BN  128
#define BK  32
#define BKP 36            // padded row stride (floats): conflict-free, 16B-aligned
#define KT  (D_IN / BK)   // 64 main k-tiles
#define NT  (KT + 1)      // +1 LoRA tile (rank 16 = 2 k-steps)
#define NSTAGE 3

#define TILE_FLOATS (BM * BKP)
#define STG_FLOATS  (2 * TILE_FLOATS)
#define STG_BYTES   (STG_FLOATS * 4)
#define SMEM_BYTES  (NSTAGE * STG_BYTES)   // 110592 B -> 2 CTAs/SM

__device__ float g_low[8192 * RANK];   // LSCALE pre-applied in kernel 1

// ---------------------------------------------------------------- helpers
__device__ __forceinline__ void cpasync16(uint32_t saddr, const void* gptr) {
    asm volatile("cp.async.cg.shared.global [%0], [%1], 16;" :: "r"(saddr), "l"(gptr));
}
__device__ __forceinline__ void mma_tf32(float c[4], const uint32_t a[4],
                                         const uint32_t b[2]) {
    asm volatile(
        "mma.sync.aligned.m16n8k8.row.col.f32.tf32.tf32.f32 "
        "{%0,%1,%2,%3}, {%4,%5,%6,%7}, {%8,%9}, {%0,%1,%2,%3};"
        : "+f"(c[0]), "+f"(c[1]), "+f"(c[2]), "+f"(c[3])
        : "r"(a[0]), "r"(a[1]), "r"(a[2]), "r"(a[3]), "r"(b[0]), "r"(b[1]));
}
__device__ __forceinline__ void ldsm4(uint32_t f[4], uint32_t saddr) {
    asm volatile("ldmatrix.sync.aligned.m8n8.x4.shared.b16 {%0,%1,%2,%3}, [%4];"
                 : "=r"(f[0]), "=r"(f[1]), "=r"(f[2]), "=r"(f[3]) : "r"(saddr));
}
__device__ __forceinline__ void ldsm2(uint32_t f[2], uint32_t saddr) {
    asm volatile("ldmatrix.sync.aligned.m8n8.x2.shared.b16 {%0,%1}, [%2];"
                 : "=r"(f[0]), "=r"(f[1]) : "r"(saddr));
}

// ---------------------------------------------------------------------------
// Kernel 1: g_low[m, r] = LSCALE * sum_k x[m,k] * lora_A[r,k]
// ---------------------------------------------------------------------------
__global__ __launch_bounds__(256)
void lora_low_kernel(const float* __restrict__ x, const float* __restrict__ lA) {
    int gw   = (blockIdx.x * blockDim.x + threadIdx.x) >> 5;
    int lane = threadIdx.x & 31;
    int mb   = gw * 4;

    const float* xr = x + (size_t)mb * D_IN;
    float acc[4][RANK];
#pragma unroll
    for (int q = 0; q < 4; q++)
#pragma unroll
        for (int r = 0; r < RANK; r++) acc[q][r] = 0.0f;

    for (int it = 0; it < D_IN / 128; it++) {
        int k = it * 128 + lane * 4;
        float4 xv[4];
#pragma unroll
        for (int q = 0; q < 4; q++)
            xv[q] = *reinterpret_cast<const float4*>(xr + (size_t)q * D_IN + k);
#pragma unroll
        for (int r = 0; r < RANK; r++) {
            float4 av = *reinterpret_cast<const float4*>(lA + (size_t)r * D_IN + k);
#pragma unroll
            for (int q = 0; q < 4; q++)
                acc[q][r] += xv[q].x * av.x + xv[q].y * av.y + xv[q].z * av.z + xv[q].w * av.w;
        }
    }

#pragma unroll
    for (int off = 16; off; off >>= 1)
#pragma unroll
        for (int q = 0; q < 4; q++)
#pragma unroll
            for (int r = 0; r < RANK; r++)
                acc[q][r] += __shfl_xor_sync(0xffffffffu, acc[q][r], off);

    if (lane == 0) {
#pragma unroll
        for (int q = 0; q < 4; q++) {
            float* dst = g_low + (size_t)(mb + q) * RANK;
#pragma unroll
            for (int j = 0; j < 4; j++) {
                float4 v = make_float4(acc[q][j * 4 + 0] * LSCALE, acc[q][j * 4 + 1] * LSCALE,
                                       acc[q][j * 4 + 2] * LSCALE, acc[q][j * 4 + 3] * LSCALE);
                *reinterpret_cast<float4*>(dst + j * 4) = v;
            }
        }
    }
}

// ---------------------------------------------------------------------------
// Kernel 2: ldmatrix + k-step software pipeline across the barrier
// ---------------------------------------------------------------------------
__device__ __forceinline__ void load_tile(float* stage,
                                          const float* __restrict__ xA,
                                          const float* __restrict__ wB,
                                          const float* __restrict__ lB,
                                          int m0, int n0, int t, int tid) {
    uint32_t sa = (uint32_t)__cvta_generic_to_shared(stage);
    uint32_t sb = sa + TILE_FLOATS * 4;
    if (t < KT) {
        const int k0 = t * BK;
#pragma unroll
        for (int i = 0; i < 4; i++) {
            int idx = tid + i * 256;
            int row = idx >> 3;
            int cg  = idx & 7;
            cpasync16(sa + (row * BKP + cg * 4) * 4, xA + (size_t)row * D_IN + k0 + cg * 4);
            cpasync16(sb + (row * BKP + cg * 4) * 4, wB + (size_t)row * D_IN + k0 + cg * 4);
        }
    } else {
#pragma unroll
        for (int i = 0; i < 2; i++) {
            int idx = tid + i * 256;
            int row = idx >> 2;
            int cg  = idx & 3;
            cpasync16(sa + (row * BKP + cg * 4) * 4, g_low + (size_t)(m0 + row) * RANK + cg * 4);
            cpasync16(sb + (row * BKP + cg * 4) * 4, lB + (size_t)(n0 + row) * RANK + cg * 4);
        }
    }
}

__global__ __launch_bounds__(256, 2)
void gemm_lora_kernel(const float* __restrict__ x, const float* __restrict__ W,
                      const float* __restrict__ bias,
                      const float* __restrict__ lB,
                      float* __restrict__ out) {
    extern __shared__ float smem[];

    const int tid  = threadIdx.x;
    const int lane = tid & 31;
    const int warp = tid >> 5;
    const int wm   = warp >> 2;
    const int wn   = warp & 3;
    const int g    = lane >> 2;
    const int tg   = lane & 3;
    const int m0   = blockIdx.y * BM;
    const int n0   = blockIdx.x * BN;

    const float* xA = x + (size_t)m0 * D_IN;
    const float* wB = W + (size_t)n0 * D_IN;

    const uint32_t sbase = (uint32_t)__cvta_generic_to_shared(smem);
    // ldmatrix per-thread byte offsets (within a stage)
    // A: matrices {rows 0-7,k 0-3}{rows 8-15,k 0-3}{rows 0-7,k 4-7}{rows 8-15,k 4-7}
    const uint32_t a_off = ((wm * 64 + (lane & 15)) * BKP + ((lane & 16) ? 4 : 0)) * 4;
    // B: x2 matrices {n 0-7,k 0-3}{n 0-7,k 4-7}; threads 0-15 provide addresses
    const uint32_t b_off = TILE_FLOATS * 4 +
                           ((wn * 32 + (lane & 7)) * BKP + ((lane & 8) ? 4 : 0)) * 4;

    float c[4][4][4];
#pragma unroll
    for (int i = 0; i < 4; i++)
#pragma unroll
        for (int j = 0; j < 4; j++)
#pragma unroll
            for (int q = 0; q < 4; q++) c[i][j][q] = 0.0f;

    uint32_t afr[2][4][4];
    uint32_t bfr[2][4][2];

#define LOAD_FRAGS(pb, sb_, ks_)                                              \
    do {                                                                      \
        _Pragma("unroll")                                                     \
        for (int i_ = 0; i_ < 4; i_++)                                        \
            ldsm4(afr[pb][i_], (sb_) + a_off + (i_ * 16 * BKP + (ks_) * 8) * 4); \
        _Pragma("unroll")                                                     \
        for (int j_ = 0; j_ < 4; j_++)                                        \
            ldsm2(bfr[pb][j_], (sb_) + b_off + (j_ * 8 * BKP + (ks_) * 8) * 4);  \
    } while (0)

    // prologue: stage 0 and 1 in flight
    load_tile(smem + 0 * STG_FLOATS, xA, wB, lB, m0, n0, 0, tid);
    asm volatile("cp.async.commit_group;");
    load_tile(smem + 1 * STG_FLOATS, xA, wB, lB, m0, n0, 1, tid);
    asm volatile("cp.async.commit_group;");

    asm volatile("cp.async.wait_group 1;");   // stage 0 resident
    __syncthreads();
    LOAD_FRAGS(0, sbase, 0);                  // (tile 0, ks 0)

    int buf = 0;
    for (int t = 0; t < KT; t++) {
        const uint32_t scur = sbase + buf * STG_BYTES;
#pragma unroll
        for (int ks = 0; ks < 4; ks++) {
            const int cur = ks & 1, nxt = cur ^ 1;
            if (ks == 3) {
                asm volatile("cp.async.wait_group 1;");   // tile t+1 resident
                __syncthreads();                          // stage t safe to overwrite
                int nb = buf + 1; if (nb == NSTAGE) nb = 0;
                LOAD_FRAGS(nxt, sbase + nb * STG_BYTES, 0);   // (t+1, ks 0)
            } else {
                LOAD_FRAGS(nxt, scur, ks + 1);
            }
            if (ks == 0) {
                if (t + 2 < NT) {
                    int pb2 = buf + 2; if (pb2 >= NSTAGE) pb2 -= NSTAGE;
                    load_tile(smem + pb2 * STG_FLOATS, xA, wB, lB, m0, n0, t + 2, tid);
                }
                asm volatile("cp.async.commit_group;");
            }
#pragma unroll
            for (int i = 0; i < 4; i++)
#pragma unroll
                for (int j = 0; j < 4; j++)
                    mma_tf32(c[i][j], afr[cur][i], bfr[cur][j]);
        }
        if (++buf == NSTAGE) buf = 0;
    }

    // LoRA tile (rank 16 = 2 k-steps); frags (ks=0) already in buffer 0
    {
        const uint32_t scur = sbase + buf * STG_BYTES;
        LOAD_FRAGS(1, scur, 1);
#pragma unroll
        for (int i = 0; i < 4; i++)
#pragma unroll
            for (int j = 0; j < 4; j++)
                mma_tf32(c[i][j], afr[0][i], bfr[0][j]);
#pragma unroll
        for (int i = 0; i < 4; i++)
#pragma unroll
            for (int j = 0; j < 4; j++)
                mma_tf32(c[i][j], afr[1][i], bfr[1][j]);
    }

    // epilogue: add bias, store float2 pairs
#pragma unroll
    for (int i = 0; i < 4; i++) {
        int m = m0 + wm * 64 + i * 16 + g;
        float* orow0 = out + (size_t)m * D_OUT;
        float* orow1 = orow0 + (size_t)8 * D_OUT;
#pragma unroll
        for (int j = 0; j < 4; j++) {
            int n = n0 + wn * 32 + j * 8 + 2 * tg;
            float b0 = bias[n];
            float b1 = bias[n + 1];
            *reinterpret_cast<float2*>(orow0 + n) =
                make_float2(c[i][j][0] + b0, c[i][j][1] + b1);
            *reinterpret_cast<float2*>(orow1 + n) =
                make_float2(c[i][j][2] + b0, c[i][j][3] + b1);
        }
    }
}

// ---------------------------------------------------------------------------
extern "C" void kernel_launch(void* const* d_in, const int* in_sizes, int n_in,
                              void* d_out, int out_size) {
    const float* x  = (const float*)d_in[0];
    const float* W  = (const float*)d_in[1];
    const float* b  = (const float*)d_in[2];
    const float* lA = (const float*)d_in[3];
    const float* lB = (const float*)d_in[4];
    float* out = (float*)d_out;

    const int M = in_sizes[0] / D_IN;   // 8192

    lora_low_kernel<<<M / 32, 256>>>(x, lA);

    cudaFuncSetAttribute(gemm_lora_kernel,
                         cudaFuncAttributeMaxDynamicSharedMemorySize, SMEM_BYTES);
    dim3 grid(D_OUT / BN, M / BM);      // (16, 64)
    gemm_lora_kernel<<<grid, 256, SMEM_BYTES>>>(x, W, b, lB, out);
}

// round 10
// speedup vs baseline: 1.4464x; 1.0284x over previous
#include <cuda_runtime.h>
#include <cstdint>

#define D_IN   2048
#define D_OUT  2048
#define RANK   16
#define LSCALE 2.0f

#define BM  128
#define BN  128
#define BK  32
#define BKP 36            // padded row stride (floats): conflict-free, 16B-aligned
#define KT  (D_IN / BK)   // 64 main k-tiles
#define NT  (KT + 1)      // +1 LoRA tile
#define NSTAGE 3

#define TILE_FLOATS (BM * BKP)
#define TILEB       (TILE_FLOATS * 4)
#define STG_FLOATS  (2 * TILE_FLOATS)
#define STG_BYTES   (STG_FLOATS * 4)
#define SMEM_BYTES  (NSTAGE * STG_BYTES)   // 110592 B -> 2 CTAs/SM

__device__ float g_low[8192 * RANK];   // LSCALE pre-applied in kernel 1

// ---------------------------------------------------------------- helpers
__device__ __forceinline__ void cpasync16(uint32_t saddr, const void* gptr) {
    asm volatile("cp.async.cg.shared.global [%0], [%1], 16;" :: "r"(saddr), "l"(gptr));
}
__device__ __forceinline__ void mma_tf32(float c[4], const uint32_t a[4],
                                         const uint32_t b[2]) {
    asm volatile(
        "mma.sync.aligned.m16n8k8.row.col.f32.tf32.tf32.f32 "
        "{%0,%1,%2,%3}, {%4,%5,%6,%7}, {%8,%9}, {%0,%1,%2,%3};"
        : "+f"(c[0]), "+f"(c[1]), "+f"(c[2]), "+f"(c[3])
        : "r"(a[0]), "r"(a[1]), "r"(a[2]), "r"(a[3]), "r"(b[0]), "r"(b[1]));
}
__device__ __forceinline__ void ldsm4(uint32_t f[4], uint32_t saddr) {
    asm volatile("ldmatrix.sync.aligned.m8n8.x4.shared.b16 {%0,%1,%2,%3}, [%4];"
                 : "=r"(f[0]), "=r"(f[1]), "=r"(f[2]), "=r"(f[3]) : "r"(saddr));
}

// ---------------------------------------------------------------------------
// Kernel 1: g_low[m, r] = LSCALE * sum_k x[m,k] * lora_A[r,k]
// ---------------------------------------------------------------------------
__global__ __launch_bounds__(256)
void lora_low_kernel(const float* __restrict__ x, const float* __restrict__ lA) {
    int gw   = (blockIdx.x * blockDim.x + threadIdx.x) >> 5;
    int lane = threadIdx.x & 31;
    int mb   = gw * 4;

    const float* xr = x + (size_t)mb * D_IN;
    float acc[4][RANK];
#pragma unroll
    for (int q = 0; q < 4; q++)
#pragma unroll
        for (int r = 0; r < RANK; r++) acc[q][r] = 0.0f;

    for (int it = 0; it < D_IN / 128; it++) {
        int k = it * 128 + lane * 4;
        float4 xv[4];
#pragma unroll
        for (int q = 0; q < 4; q++)
            xv[q] = *reinterpret_cast<const float4*>(xr + (size_t)q * D_IN + k);
#pragma unroll
        for (int r = 0; r < RANK; r++) {
            float4 av = *reinterpret_cast<const float4*>(lA + (size_t)r * D_IN + k);
#pragma unroll
            for (int q = 0; q < 4; q++)
                acc[q][r] += xv[q].x * av.x + xv[q].y * av.y + xv[q].z * av.z + xv[q].w * av.w;
        }
    }

#pragma unroll
    for (int off = 16; off; off >>= 1)
#pragma unroll
        for (int q = 0; q < 4; q++)
#pragma unroll
            for (int r = 0; r < RANK; r++)
                acc[q][r] += __shfl_xor_sync(0xffffffffu, acc[q][r], off);

    if (lane == 0) {
#pragma unroll
        for (int q = 0; q < 4; q++) {
            float* dst = g_low + (size_t)(mb + q) * RANK;
#pragma unroll
            for (int j = 0; j < 4; j++) {
                float4 v = make_float4(acc[q][j * 4 + 0] * LSCALE, acc[q][j * 4 + 1] * LSCALE,
                                       acc[q][j * 4 + 2] * LSCALE, acc[q][j * 4 + 3] * LSCALE);
                *reinterpret_cast<float4*>(dst + j * 4) = v;
            }
        }
    }
}

// ---------------------------------------------------------------------------
// Kernel 2: ldmatrix(x4 A + paired-x4 B), k-pipeline across barrier,
// triple-unrolled mainloop (constant buffer offsets), cp.async spread over ks
// ---------------------------------------------------------------------------
__device__ __forceinline__ void load_tile_full(float* stage,
                                               const float* __restrict__ xA,
                                               const float* __restrict__ wB,
                                               int k0, int tid) {
    uint32_t sa = (uint32_t)__cvta_generic_to_shared(stage);
    uint32_t sb = sa + TILEB;
#pragma unroll
    for (int i = 0; i < 4; i++) {
        int idx = tid + i * 256;
        int row = idx >> 3;
        int cg  = idx & 7;
        cpasync16(sa + (row * BKP + cg * 4) * 4, xA + (size_t)row * D_IN + k0 + cg * 4);
        cpasync16(sb + (row * BKP + cg * 4) * 4, wB + (size_t)row * D_IN + k0 + cg * 4);
    }
}

__global__ __launch_bounds__(256, 2)
void gemm_lora_kernel(const float* __restrict__ x, const float* __restrict__ W,
                      const float* __restrict__ bias,
                      const float* __restrict__ lB,
                      float* __restrict__ out) {
    extern __shared__ float smem[];

    const int tid  = threadIdx.x;
    const int lane = tid & 31;
    const int warp = tid >> 5;
    const int wm   = warp >> 2;
    const int wn   = warp & 3;
    const int g    = lane >> 2;
    const int tg   = lane & 3;
    const int m0   = blockIdx.y * BM;
    const int n0   = blockIdx.x * BN;

    const float* xA = x + (size_t)m0 * D_IN;
    const float* wB = W + (size_t)n0 * D_IN;

    const uint32_t sbase = (uint32_t)__cvta_generic_to_shared(smem);
    // A: x4 matrices {m0-7,k0-3}{m8-15,k0-3}{m0-7,k4-7}{m8-15,k4-7}
    const uint32_t a_off = ((wm * 64 + (lane & 15)) * BKP + ((lane & 16) ? 4 : 0)) * 4;
    // B paired x4: {n0-7,k0-3}{n0-7,k4-7}{n8-15,k0-3}{n8-15,k4-7}
    const uint32_t b_off = TILEB +
        ((wn * 32 + ((lane & 16) >> 1) + (lane & 7)) * BKP + ((lane & 8) ? 4 : 0)) * 4;

    float c[4][4][4];
#pragma unroll
    for (int i = 0; i < 4; i++)
#pragma unroll
        for (int j = 0; j < 4; j++)
#pragma unroll
            for (int q = 0; q < 4; q++) c[i][j][q] = 0.0f;

    uint32_t afr[2][4][4];
    uint32_t bfr[2][4][2];

#define LOAD_FRAGS(pb, SBX, ks_)                                                \
    do {                                                                        \
        _Pragma("unroll")                                                       \
        for (int i_ = 0; i_ < 4; i_++)                                          \
            ldsm4(afr[pb][i_], (SBX) + a_off + (i_ * 16 * BKP + (ks_) * 8) * 4);\
        _Pragma("unroll")                                                       \
        for (int jp_ = 0; jp_ < 2; jp_++)                                       \
            ldsm4(&bfr[pb][jp_ * 2][0],                                         \
                  (SBX) + b_off + (jp_ * 16 * BKP + (ks_) * 8) * 4);            \
    } while (0)

#define MMA_ALL(cb)                                                             \
    do {                                                                        \
        _Pragma("unroll")                                                       \
        for (int i_ = 0; i_ < 4; i_++)                                          \
            _Pragma("unroll")                                                   \
            for (int j_ = 0; j_ < 4; j_++)                                      \
                mma_tf32(c[i_][j_], afr[cb][i_], bfr[cb][j_]);                  \
    } while (0)

    // part p (0..3) of tile tn load: exactly one 256-chunk -> rows 0..127 total
#define LOAD_PART(PBX, tn_, p_)                                                 \
    do {                                                                        \
        if ((tn_) < KT) {                                                       \
            const int k0_ = (tn_) * BK;                                         \
            int idx_ = tid + (p_) * 256;                                        \
            int row_ = idx_ >> 3, cg_ = idx_ & 7;                               \
            cpasync16((PBX) + (row_ * BKP + cg_ * 4) * 4,                       \
                      xA + (size_t)row_ * D_IN + k0_ + cg_ * 4);                \
            cpasync16((PBX) + TILEB + (row_ * BKP + cg_ * 4) * 4,               \
                      wB + (size_t)row_ * D_IN + k0_ + cg_ * 4);                \
        } else if ((tn_) == KT && (p_) < 2) {                                   \
            int idx_ = tid + (p_) * 256;                                        \
            int row_ = idx_ >> 2, cg_ = idx_ & 3;                               \
            cpasync16((PBX) + (row_ * BKP + cg_ * 4) * 4,                       \
                      g_low + (size_t)(m0 + row_) * RANK + cg_ * 4);            \
            cpasync16((PBX) + TILEB + (row_ * BKP + cg_ * 4) * 4,               \
                      lB + (size_t)(n0 + row_) * RANK + cg_ * 4);               \
        }                                                                       \
    } while (0)

#define TILE_BODY(BUFC)                                                         \
    do {                                                                        \
        const uint32_t SB = sbase + (BUFC) * STG_BYTES;                         \
        const uint32_t NB = sbase + (((BUFC) + 1) % NSTAGE) * STG_BYTES;        \
        const uint32_t PB = sbase + (((BUFC) + 2) % NSTAGE) * STG_BYTES;        \
        const int tn = t + 2;                                                   \
        LOAD_PART(PB, tn, 0);                                                   \
        LOAD_FRAGS(1, SB, 1);                                                   \
        MMA_ALL(0);                                                             \
        LOAD_PART(PB, tn, 1);                                                   \
        LOAD_FRAGS(0, SB, 2);                                                   \
        MMA_ALL(1);                                                             \
        LOAD_PART(PB, tn, 2);                                                   \
        LOAD_FRAGS(1, SB, 3);                                                   \
        MMA_ALL(0);                                                             \
        LOAD_PART(PB, tn, 3);                                                   \
        asm volatile("cp.async.commit_group;");                                 \
        asm volatile("cp.async.wait_group 1;");                                 \
        __syncthreads();                                                        \
        LOAD_FRAGS(0, NB, 0);                                                   \
        MMA_ALL(1);                                                             \
        t++;                                                                    \
    } while (0)

    // prologue: tiles 0 and 1 fully in flight
    load_tile_full(smem + 0 * STG_FLOATS, xA, wB, 0, tid);
    asm volatile("cp.async.commit_group;");
    load_tile_full(smem + 1 * STG_FLOATS, xA, wB, BK, tid);
    asm volatile("cp.async.commit_group;");

    asm volatile("cp.async.wait_group 1;");   // tile 0 resident
    __syncthreads();
    LOAD_FRAGS(0, sbase, 0);                  // (tile 0, ks 0)

    int t = 0;
#pragma unroll 1
    for (int it = 0; it < KT / 3; it++) {     // 21 triples -> t = 0..62
        TILE_BODY(0);
        TILE_BODY(1);
        TILE_BODY(2);
    }
    TILE_BODY(0);                             // t = 63

    // LoRA tile (buffer 1): frags[0] already hold ks0
    {
        const uint32_t SB = sbase + 1 * STG_BYTES;
        LOAD_FRAGS(1, SB, 1);
        MMA_ALL(0);
        MMA_ALL(1);
    }

    // epilogue: add bias, store float2 pairs
#pragma unroll
    for (int i = 0; i < 4; i++) {
        int m = m0 + wm * 64 + i * 16 + g;
        float* orow0 = out + (size_t)m * D_OUT;
        float* orow1 = orow0 + (size_t)8 * D_OUT;
#pragma unroll
        for (int j = 0; j < 4; j++) {
            int n = n0 + wn * 32 + j * 8 + 2 * tg;
            float b0 = bias[n];
            float b1 = bias[n + 1];
            *reinterpret_cast<float2*>(orow0 + n) =
                make_float2(c[i][j][0] + b0, c[i][j][1] + b1);
            *reinterpret_cast<float2*>(orow1 + n) =
                make_float2(c[i][j][2] + b0, c[i][j][3] + b1);
        }
    }
}

// ---------------------------------------------------------------------------
extern "C" void kernel_launch(void* const* d_in, const int* in_sizes, int n_in,
                              void* d_out, int out_size) {
    const float* x  = (const float*)d_in[0];
    const float* W  = (const float*)d_in[1];
    const float* b  = (const float*)d_in[2];
    const float* lA = (const float*)d_in[3];
    const float* lB = (const float*)d_in[4];
    float* out = (float*)d_out;

    const int M = in_sizes[0] / D_IN;   // 8192

    lora_low_kernel<<<M / 32, 256>>>(x, lA);

    cudaFuncSetAttribute(gemm_lora_kernel,
                         cudaFuncAttributeMaxDynamicSharedMemorySize, SMEM_BYTES);
    dim3 grid(D_OUT / BN, M / BM);      // (16, 64)
    gemm_lora_kernel<<<grid, 256, SMEM_BYTES>>>(x, W, b, lB, out);
}

// round 11
// speedup vs baseline: 1.6346x; 1.1301x over previous
#include <cuda_runtime.h>
#include <cstdint>

#define D_IN   2048
#define D_OUT  2048
#define RANK   16
#define LSCALE 2.0f

#define BM  128
#define BN  128
#define BK  32
#define BKP 36            // padded row stride (floats): conflict-free, 16B-aligned
#define KT  (D_IN / BK)   // 64 main k-tiles
#define NSTAGE 3
#define NTHREADS 128

#define TILE_FLOATS (BM * BKP)
#define TILEB       (TILE_FLOATS * 4)
#define STG_FLOATS  (2 * TILE_FLOATS)
#define STG_BYTES   (STG_FLOATS * 4)
#define SMEM_BYTES  (NSTAGE * STG_BYTES)   // 110592 B x 2 CTAs = 216 KB/SM

__device__ float g_low[8192 * RANK];   // LSCALE pre-applied in kernel 1

// ---------------------------------------------------------------- helpers
__device__ __forceinline__ void cpasync16(uint32_t saddr, const void* gptr) {
    asm volatile("cp.async.cg.shared.global [%0], [%1], 16;" :: "r"(saddr), "l"(gptr));
}
__device__ __forceinline__ void mma_tf32(float c[4], const uint32_t a[4],
                                         const uint32_t b[2]) {
    asm volatile(
        "mma.sync.aligned.m16n8k8.row.col.f32.tf32.tf32.f32 "
        "{%0,%1,%2,%3}, {%4,%5,%6,%7}, {%8,%9}, {%0,%1,%2,%3};"
        : "+f"(c[0]), "+f"(c[1]), "+f"(c[2]), "+f"(c[3])
        : "r"(a[0]), "r"(a[1]), "r"(a[2]), "r"(a[3]), "r"(b[0]), "r"(b[1]));
}
__device__ __forceinline__ void ldsm4(uint32_t f[4], uint32_t saddr) {
    asm volatile("ldmatrix.sync.aligned.m8n8.x4.shared.b16 {%0,%1,%2,%3}, [%4];"
                 : "=r"(f[0]), "=r"(f[1]), "=r"(f[2]), "=r"(f[3]) : "r"(saddr));
}

// ---------------------------------------------------------------------------
// Kernel 1: g_low[m, r] = LSCALE * sum_k x[m,k] * lora_A[r,k]
// ---------------------------------------------------------------------------
__global__ __launch_bounds__(256)
void lora_low_kernel(const float* __restrict__ x, const float* __restrict__ lA) {
    int gw   = (blockIdx.x * blockDim.x + threadIdx.x) >> 5;
    int lane = threadIdx.x & 31;
    int mb   = gw * 4;

    const float* xr = x + (size_t)mb * D_IN;
    float acc[4][RANK];
#pragma unroll
    for (int q = 0; q < 4; q++)
#pragma unroll
        for (int r = 0; r < RANK; r++) acc[q][r] = 0.0f;

    for (int it = 0; it < D_IN / 128; it++) {
        int k = it * 128 + lane * 4;
        float4 xv[4];
#pragma unroll
        for (int q = 0; q < 4; q++)
            xv[q] = *reinterpret_cast<const float4*>(xr + (size_t)q * D_IN + k);
#pragma unroll
        for (int r = 0; r < RANK; r++) {
            float4 av = *reinterpret_cast<const float4*>(lA + (size_t)r * D_IN + k);
#pragma unroll
            for (int q = 0; q < 4; q++)
                acc[q][r] += xv[q].x * av.x + xv[q].y * av.y + xv[q].z * av.z + xv[q].w * av.w;
        }
    }

#pragma unroll
    for (int off = 16; off; off >>= 1)
#pragma unroll
        for (int q = 0; q < 4; q++)
#pragma unroll
            for (int r = 0; r < RANK; r++)
                acc[q][r] += __shfl_xor_sync(0xffffffffu, acc[q][r], off);

    if (lane == 0) {
#pragma unroll
        for (int q = 0; q < 4; q++) {
            float* dst = g_low + (size_t)(mb + q) * RANK;
#pragma unroll
            for (int j = 0; j < 4; j++) {
                float4 v = make_float4(acc[q][j * 4 + 0] * LSCALE, acc[q][j * 4 + 1] * LSCALE,
                                       acc[q][j * 4 + 2] * LSCALE, acc[q][j * 4 + 3] * LSCALE);
                *reinterpret_cast<float4*>(dst + j * 4) = v;
            }
        }
    }
}

// ---------------------------------------------------------------------------
// Kernel 2: 128x128 tile, 4 warps, warp tile 64x64 (halved smem traffic/FLOP)
// ldmatrix x4 A+B, k-pipeline across barrier, triple-unrolled buffer indices
// ---------------------------------------------------------------------------
__device__ __forceinline__ void load_tile_full(float* stage,
                                               const float* __restrict__ xA,
                                               const float* __restrict__ wB,
                                               int k0, int tid) {
    uint32_t sa = (uint32_t)__cvta_generic_to_shared(stage);
    uint32_t sb = sa + TILEB;
#pragma unroll
    for (int i = 0; i < 8; i++) {
        int idx = tid + i * NTHREADS;   // 0..1023
        int row = idx >> 3;
        int cg  = idx & 7;
        cpasync16(sa + (row * BKP + cg * 4) * 4, xA + (size_t)row * D_IN + k0 + cg * 4);
        cpasync16(sb + (row * BKP + cg * 4) * 4, wB + (size_t)row * D_IN + k0 + cg * 4);
    }
}

__global__ __launch_bounds__(NTHREADS, 2)
void gemm_lora_kernel(const float* __restrict__ x, const float* __restrict__ W,
                      const float* __restrict__ bias,
                      const float* __restrict__ lB,
                      float* __restrict__ out) {
    extern __shared__ float smem[];

    const int tid  = threadIdx.x;
    const int lane = tid & 31;
    const int warp = tid >> 5;     // 0..3
    const int wm   = warp >> 1;    // 0..1
    const int wn   = warp & 1;     // 0..1
    const int g    = lane >> 2;
    const int tg   = lane & 3;
    const int m0   = blockIdx.y * BM;
    const int n0   = blockIdx.x * BN;

    const float* xA = x + (size_t)m0 * D_IN;
    const float* wB = W + (size_t)n0 * D_IN;

    const uint32_t sbase = (uint32_t)__cvta_generic_to_shared(smem);
    // A x4: {m0-7,k0-3}{m8-15,k0-3}{m0-7,k4-7}{m8-15,k4-7}
    const uint32_t a_off = ((wm * 64 + (lane & 15)) * BKP + ((lane & 16) ? 4 : 0)) * 4;
    // B paired x4: {n0-7,k0-3}{n0-7,k4-7}{n8-15,k0-3}{n8-15,k4-7}
    const uint32_t b_off = TILEB +
        ((wn * 64 + ((lane & 16) >> 1) + (lane & 7)) * BKP + ((lane & 8) ? 4 : 0)) * 4;

    float c[4][8][4];
#pragma unroll
    for (int i = 0; i < 4; i++)
#pragma unroll
        for (int j = 0; j < 8; j++)
#pragma unroll
            for (int q = 0; q < 4; q++) c[i][j][q] = 0.0f;

    uint32_t afr[2][4][4];
    uint32_t bfr[2][8][2];

#define LOAD_FRAGS(pb, SBX, ks_)                                                \
    do {                                                                        \
        _Pragma("unroll")                                                       \
        for (int i_ = 0; i_ < 4; i_++)                                          \
            ldsm4(afr[pb][i_], (SBX) + a_off + (i_ * 16 * BKP + (ks_) * 8) * 4);\
        _Pragma("unroll")                                                       \
        for (int jp_ = 0; jp_ < 4; jp_++)                                       \
            ldsm4(&bfr[pb][jp_ * 2][0],                                         \
                  (SBX) + b_off + (jp_ * 16 * BKP + (ks_) * 8) * 4);            \
    } while (0)

#define MMA_ALL(cb)                                                             \
    do {                                                                        \
        _Pragma("unroll")                                                       \
        for (int i_ = 0; i_ < 4; i_++)                                          \
            _Pragma("unroll")                                                   \
            for (int j_ = 0; j_ < 8; j_++)                                      \
                mma_tf32(c[i_][j_], afr[cb][i_], bfr[cb][j_]);                  \
    } while (0)

    // part p (0..3) of tile tn: 2 chunks of 128 per matrix (normal),
    // 1 chunk per matrix (lora) -> totals 1024 / 512 chunks per matrix
#define LOAD_PART(PBX, tn_, p_)                                                 \
    do {                                                                        \
        if ((tn_) < KT) {                                                       \
            const int k0_ = (tn_) * BK;                                         \
            _Pragma("unroll")                                                   \
            for (int q_ = 0; q_ < 2; q_++) {                                    \
                int idx_ = tid + ((p_) * 2 + q_) * NTHREADS;  /* 0..1023 */     \
                int row_ = idx_ >> 3, cg_ = idx_ & 7;                           \
                cpasync16((PBX) + (row_ * BKP + cg_ * 4) * 4,                   \
                          xA + (size_t)row_ * D_IN + k0_ + cg_ * 4);            \
                cpasync16((PBX) + TILEB + (row_ * BKP + cg_ * 4) * 4,           \
                          wB + (size_t)row_ * D_IN + k0_ + cg_ * 4);            \
            }                                                                   \
        } else if ((tn_) == KT) {                                               \
            int idx_ = tid + (p_) * NTHREADS;                 /* 0..511 */      \
            int row_ = idx_ >> 2, cg_ = idx_ & 3;                               \
            cpasync16((PBX) + (row_ * BKP + cg_ * 4) * 4,                       \
                      g_low + (size_t)(m0 + row_) * RANK + cg_ * 4);            \
            cpasync16((PBX) + TILEB + (row_ * BKP + cg_ * 4) * 4,               \
                      lB + (size_t)(n0 + row_) * RANK + cg_ * 4);               \
        }                                                                       \
    } while (0)

#define TILE_BODY(BUFC)                                                         \
    do {                                                                        \
        const uint32_t SB = sbase + (BUFC) * STG_BYTES;                         \
        const uint32_t NB = sbase + (((BUFC) + 1) % NSTAGE) * STG_BYTES;        \
        const uint32_t PB = sbase + (((BUFC) + 2) % NSTAGE) * STG_BYTES;        \
        const int tn = t + 2;                                                   \
        LOAD_PART(PB, tn, 0);                                                   \
        LOAD_FRAGS(1, SB, 1);                                                   \
        MMA_ALL(0);                                                             \
        LOAD_PART(PB, tn, 1);                                                   \
        LOAD_FRAGS(0, SB, 2);                                                   \
        MMA_ALL(1);                                                             \
        LOAD_PART(PB, tn, 2);                                                   \
        LOAD_FRAGS(1, SB, 3);                                                   \
        MMA_ALL(0);                                                             \
        LOAD_PART(PB, tn, 3);                                                   \
        asm volatile("cp.async.commit_group;");                                 \
        asm volatile("cp.async.wait_group 1;");                                 \
        __syncthreads();                                                        \
        LOAD_FRAGS(0, NB, 0);                                                   \
        MMA_ALL(1);                                                             \
        t++;                                                                    \
    } while (0)

    // prologue: tiles 0 and 1 fully in flight
    load_tile_full(smem + 0 * STG_FLOATS, xA, wB, 0, tid);
    asm volatile("cp.async.commit_group;");
    load_tile_full(smem + 1 * STG_FLOATS, xA, wB, BK, tid);
    asm volatile("cp.async.commit_group;");

    asm volatile("cp.async.wait_group 1;");   // tile 0 resident
    __syncthreads();
    LOAD_FRAGS(0, sbase, 0);                  // (tile 0, ks 0)

    int t = 0;
#pragma unroll 1
    for (int it = 0; it < KT / 3; it++) {     // 21 triples -> t = 0..62
        TILE_BODY(0);
        TILE_BODY(1);
        TILE_BODY(2);
    }
    TILE_BODY(0);                             // t = 63

    // LoRA tile (buffer 1): frags[0] already hold ks0
    {
        const uint32_t SB = sbase + 1 * STG_BYTES;
        LOAD_FRAGS(1, SB, 1);
        MMA_ALL(0);
        MMA_ALL(1);
    }

    // epilogue: add bias, store float2 pairs
#pragma unroll
    for (int i = 0; i < 4; i++) {
        int m = m0 + wm * 64 + i * 16 + g;
        float* orow0 = out + (size_t)m * D_OUT;
        float* orow1 = orow0 + (size_t)8 * D_OUT;
#pragma unroll
        for (int j = 0; j < 8; j++) {
            int n = n0 + wn * 64 + j * 8 + 2 * tg;
            float b0 = bias[n];
            float b1 = bias[n + 1];
            *reinterpret_cast<float2*>(orow0 + n) =
                make_float2(c[i][j][0] + b0, c[i][j][1] + b1);
            *reinterpret_cast<float2*>(orow1 + n) =
                make_float2(c[i][j][2] + b0, c[i][j][3] + b1);
        }
    }
}

// ---------------------------------------------------------------------------
extern "C" void kernel_launch(void* const* d_in, const int* in_sizes, int n_in,
                              void* d_out, int out_size) {
    const float* x  = (const float*)d_in[0];
    const float* W  = (const float*)d_in[1];
    const float* b  = (const float*)d_in[2];
    const float* lA = (const float*)d_in[3];
    const float* lB = (const float*)d_in[4];
    float* out = (float*)d_out;

    const int M = in_sizes[0] / D_IN;   // 8192

    lora_low_kernel<<<M / 32, 256>>>(x, lA);

    cudaFuncSetAttribute(gemm_lora_kernel,
                         cudaFuncAttributeMaxDynamicSharedMemorySize, SMEM_BYTES);
    dim3 grid(D_OUT / BN, M / BM);      // (16, 64)
    gemm_lora_kernel<<<grid, NTHREADS, SMEM_BYTES>>>(x, W, b, lB, out);
}

// round 12
// speedup vs baseline: 1.6922x; 1.0353x over previous
#include <cuda_runtime.h>
#include <cstdint>

#define D_IN   2048
#define D_OUT  2048
#define RANK   16
#define LSCALE 2.0f

#define BM  128
#define BN  128
#define BK  32
#define BKP 36            // padded row stride (floats): conflict-free, 16B-aligned
#define KT  (D_IN / BK)   // 64 main k-tiles
#define NSTAGE 3
#define NTHREADS 128

#define TILE_FLOATS (BM * BKP)
#define TILEB       (TILE_FLOATS * 4)
#define STG_FLOATS  (2 * TILE_FLOATS)
#define STG_BYTES   (STG_FLOATS * 4)
#define SMEM_BYTES  (NSTAGE * STG_BYTES)   // 110592 B x 2 CTAs = 216 KB/SM

__device__ float g_low[8192 * RANK];   // LSCALE pre-applied in kernel 1

// ---------------------------------------------------------------- helpers
__device__ __forceinline__ void cpasync16(uint32_t saddr, const void* gptr) {
    asm volatile("cp.async.cg.shared.global [%0], [%1], 16;" :: "r"(saddr), "l"(gptr));
}
__device__ __forceinline__ void mma_tf32(float c[4], const uint32_t a[4],
                                         const uint32_t b[2]) {
    asm volatile(
        "mma.sync.aligned.m16n8k8.row.col.f32.tf32.tf32.f32 "
        "{%0,%1,%2,%3}, {%4,%5,%6,%7}, {%8,%9}, {%0,%1,%2,%3};"
        : "+f"(c[0]), "+f"(c[1]), "+f"(c[2]), "+f"(c[3])
        : "r"(a[0]), "r"(a[1]), "r"(a[2]), "r"(a[3]), "r"(b[0]), "r"(b[1]));
}
__device__ __forceinline__ void ldsm4(uint32_t f[4], uint32_t saddr) {
    asm volatile("ldmatrix.sync.aligned.m8n8.x4.shared.b16 {%0,%1,%2,%3}, [%4];"
                 : "=r"(f[0]), "=r"(f[1]), "=r"(f[2]), "=r"(f[3]) : "r"(saddr));
}

// ---------------------------------------------------------------------------
// Kernel 1 (PDL primary): g_low[m, r] = LSCALE * sum_k x[m,k] * lora_A[r,k]
// Triggers programmatic launch completion at entry so the GEMM overlaps.
// ---------------------------------------------------------------------------
__global__ __launch_bounds__(256)
void lora_low_kernel(const float* __restrict__ x, const float* __restrict__ lA) {
    cudaTriggerProgrammaticLaunchCompletion();

    int gw   = (blockIdx.x * blockDim.x + threadIdx.x) >> 5;
    int lane = threadIdx.x & 31;
    int mb   = gw * 4;

    const float* xr = x + (size_t)mb * D_IN;
    float acc[4][RANK];
#pragma unroll
    for (int q = 0; q < 4; q++)
#pragma unroll
        for (int r = 0; r < RANK; r++) acc[q][r] = 0.0f;

    for (int it = 0; it < D_IN / 128; it++) {
        int k = it * 128 + lane * 4;
        float4 xv[4];
#pragma unroll
        for (int q = 0; q < 4; q++)
            xv[q] = *reinterpret_cast<const float4*>(xr + (size_t)q * D_IN + k);
#pragma unroll
        for (int r = 0; r < RANK; r++) {
            float4 av = *reinterpret_cast<const float4*>(lA + (size_t)r * D_IN + k);
#pragma unroll
            for (int q = 0; q < 4; q++)
                acc[q][r] += xv[q].x * av.x + xv[q].y * av.y + xv[q].z * av.z + xv[q].w * av.w;
        }
    }

#pragma unroll
    for (int off = 16; off; off >>= 1)
#pragma unroll
        for (int q = 0; q < 4; q++)
#pragma unroll
            for (int r = 0; r < RANK; r++)
                acc[q][r] += __shfl_xor_sync(0xffffffffu, acc[q][r], off);

    if (lane == 0) {
#pragma unroll
        for (int q = 0; q < 4; q++) {
            float* dst = g_low + (size_t)(mb + q) * RANK;
#pragma unroll
            for (int j = 0; j < 4; j++) {
                float4 v = make_float4(acc[q][j * 4 + 0] * LSCALE, acc[q][j * 4 + 1] * LSCALE,
                                       acc[q][j * 4 + 2] * LSCALE, acc[q][j * 4 + 3] * LSCALE);
                *reinterpret_cast<float4*>(dst + j * 4) = v;
            }
        }
    }
}

// ---------------------------------------------------------------------------
// Kernel 2 (PDL secondary): 128x128 tile, 4 warps, 64x64 warp tiles,
// ldmatrix x4 A+B, k-pipeline across barrier, triple-unrolled buffers.
// cudaGridDependencySynchronize() before the g_low-consuming prefetch.
// ---------------------------------------------------------------------------
__device__ __forceinline__ void load_tile_full(float* stage,
                                               const float* __restrict__ xA,
                                               const float* __restrict__ wB,
                                               int k0, int tid) {
    uint32_t sa = (uint32_t)__cvta_generic_to_shared(stage);
    uint32_t sb = sa + TILEB;
#pragma unroll
    for (int i = 0; i < 8; i++) {
        int idx = tid + i * NTHREADS;   // 0..1023
        int row = idx >> 3;
        int cg  = idx & 7;
        cpasync16(sa + (row * BKP + cg * 4) * 4, xA + (size_t)row * D_IN + k0 + cg * 4);
        cpasync16(sb + (row * BKP + cg * 4) * 4, wB + (size_t)row * D_IN + k0 + cg * 4);
    }
}

__global__ __launch_bounds__(NTHREADS, 2)
void gemm_lora_kernel(const float* __restrict__ x, const float* __restrict__ W,
                      const float* __restrict__ bias,
                      const float* __restrict__ lB,
                      float* __restrict__ out) {
    extern __shared__ float smem[];

    const int tid  = threadIdx.x;
    const int lane = tid & 31;
    const int warp = tid >> 5;     // 0..3
    const int wm   = warp >> 1;    // 0..1
    const int wn   = warp & 1;     // 0..1
    const int g    = lane >> 2;
    const int tg   = lane & 3;
    const int m0   = blockIdx.y * BM;
    const int n0   = blockIdx.x * BN;

    const float* xA = x + (size_t)m0 * D_IN;
    const float* wB = W + (size_t)n0 * D_IN;

    const uint32_t sbase = (uint32_t)__cvta_generic_to_shared(smem);
    // A x4: {m0-7,k0-3}{m8-15,k0-3}{m0-7,k4-7}{m8-15,k4-7}
    const uint32_t a_off = ((wm * 64 + (lane & 15)) * BKP + ((lane & 16) ? 4 : 0)) * 4;
    // B paired x4: {n0-7,k0-3}{n0-7,k4-7}{n8-15,k0-3}{n8-15,k4-7}
    const uint32_t b_off = TILEB +
        ((wn * 64 + ((lane & 16) >> 1) + (lane & 7)) * BKP + ((lane & 8) ? 4 : 0)) * 4;

    float c[4][8][4];
#pragma unroll
    for (int i = 0; i < 4; i++)
#pragma unroll
        for (int j = 0; j < 8; j++)
#pragma unroll
            for (int q = 0; q < 4; q++) c[i][j][q] = 0.0f;

    uint32_t afr[2][4][4];
    uint32_t bfr[2][8][2];

#define LOAD_FRAGS(pb, SBX, ks_)                                                \
    do {                                                                        \
        _Pragma("unroll")                                                       \
        for (int i_ = 0; i_ < 4; i_++)                                          \
            ldsm4(afr[pb][i_], (SBX) + a_off + (i_ * 16 * BKP + (ks_) * 8) * 4);\
        _Pragma("unroll")                                                       \
        for (int jp_ = 0; jp_ < 4; jp_++)                                       \
            ldsm4(&bfr[pb][jp_ * 2][0],                                         \
                  (SBX) + b_off + (jp_ * 16 * BKP + (ks_) * 8) * 4);            \
    } while (0)

#define MMA_ALL(cb)                                                             \
    do {                                                                        \
        _Pragma("unroll")                                                       \
        for (int i_ = 0; i_ < 4; i_++)                                          \
            _Pragma("unroll")                                                   \
            for (int j_ = 0; j_ < 8; j_++)                                      \
                mma_tf32(c[i_][j_], afr[cb][i_], bfr[cb][j_]);                  \
    } while (0)

#define LOAD_PART(PBX, tn_, p_)                                                 \
    do {                                                                        \
        if ((tn_) < KT) {                                                       \
            const int k0_ = (tn_) * BK;                                         \
            _Pragma("unroll")                                                   \
            for (int q_ = 0; q_ < 2; q_++) {                                    \
                int idx_ = tid + ((p_) * 2 + q_) * NTHREADS;  /* 0..1023 */     \
                int row_ = idx_ >> 3, cg_ = idx_ & 7;                           \
                cpasync16((PBX) + (row_ * BKP + cg_ * 4) * 4,                   \
                          xA + (size_t)row_ * D_IN + k0_ + cg_ * 4);            \
                cpasync16((PBX) + TILEB + (row_ * BKP + cg_ * 4) * 4,           \
                          wB + (size_t)row_ * D_IN + k0_ + cg_ * 4);            \
            }                                                                   \
        } else if ((tn_) == KT) {                                               \
            int idx_ = tid + (p_) * NTHREADS;                 /* 0..511 */      \
            int row_ = idx_ >> 2, cg_ = idx_ & 3;                               \
            cpasync16((PBX) + (row_ * BKP + cg_ * 4) * 4,                       \
                      g_low + (size_t)(m0 + row_) * RANK + cg_ * 4);            \
            cpasync16((PBX) + TILEB + (row_ * BKP + cg_ * 4) * 4,               \
                      lB + (size_t)(n0 + row_) * RANK + cg_ * 4);               \
        }                                                                       \
    } while (0)

#define TILE_BODY(BUFC)                                                         \
    do {                                                                        \
        const uint32_t SB = sbase + (BUFC) * STG_BYTES;                         \
        const uint32_t NB = sbase + (((BUFC) + 1) % NSTAGE) * STG_BYTES;        \
        const uint32_t PB = sbase + (((BUFC) + 2) % NSTAGE) * STG_BYTES;        \
        const int tn = t + 2;                                                   \
        LOAD_PART(PB, tn, 0);                                                   \
        LOAD_FRAGS(1, SB, 1);                                                   \
        MMA_ALL(0);                                                             \
        LOAD_PART(PB, tn, 1);                                                   \
        LOAD_FRAGS(0, SB, 2);                                                   \
        MMA_ALL(1);                                                             \
        LOAD_PART(PB, tn, 2);                                                   \
        LOAD_FRAGS(1, SB, 3);                                                   \
        MMA_ALL(0);                                                             \
        LOAD_PART(PB, tn, 3);                                                   \
        asm volatile("cp.async.commit_group;");                                 \
        asm volatile("cp.async.wait_group 1;");                                 \
        __syncthreads();                                                        \
        LOAD_FRAGS(0, NB, 0);                                                   \
        MMA_ALL(1);                                                             \
        t++;                                                                    \
    } while (0)

    // prologue: tiles 0 and 1 fully in flight
    load_tile_full(smem + 0 * STG_FLOATS, xA, wB, 0, tid);
    asm volatile("cp.async.commit_group;");
    load_tile_full(smem + 1 * STG_FLOATS, xA, wB, BK, tid);
    asm volatile("cp.async.commit_group;");

    asm volatile("cp.async.wait_group 1;");   // tile 0 resident
    __syncthreads();
    LOAD_FRAGS(0, sbase, 0);                  // (tile 0, ks 0)

    int t = 0;
#pragma unroll 1
    for (int it = 0; it < 20; it++) {         // t = 0..59
        TILE_BODY(0);
        TILE_BODY(1);
        TILE_BODY(2);
    }
    TILE_BODY(0);                             // t = 60
    TILE_BODY(1);                             // t = 61

    // kernel1's g_low must be complete before t=62 prefetches the LoRA tile
    cudaGridDependencySynchronize();

    TILE_BODY(2);                             // t = 62 (loads g_low / lB tile)
    TILE_BODY(0);                             // t = 63

    // LoRA tile (buffer 1): frags[0] already hold ks0
    {
        const uint32_t SB = sbase + 1 * STG_BYTES;
        LOAD_FRAGS(1, SB, 1);
        MMA_ALL(0);
        MMA_ALL(1);
    }

    // epilogue: add bias, store float2 pairs
#pragma unroll
    for (int i = 0; i < 4; i++) {
        int m = m0 + wm * 64 + i * 16 + g;
        float* orow0 = out + (size_t)m * D_OUT;
        float* orow1 = orow0 + (size_t)8 * D_OUT;
#pragma unroll
        for (int j = 0; j < 8; j++) {
            int n = n0 + wn * 64 + j * 8 + 2 * tg;
            float b0 = bias[n];
            float b1 = bias[n + 1];
            *reinterpret_cast<float2*>(orow0 + n) =
                make_float2(c[i][j][0] + b0, c[i][j][1] + b1);
            *reinterpret_cast<float2*>(orow1 + n) =
                make_float2(c[i][j][2] + b0, c[i][j][3] + b1);
        }
    }
}

// ---------------------------------------------------------------------------
extern "C" void kernel_launch(void* const* d_in, const int* in_sizes, int n_in,
                              void* d_out, int out_size) {
    const float* x  = (const float*)d_in[0];
    const float* W  = (const float*)d_in[1];
    const float* b  = (const float*)d_in[2];
    const float* lA = (const float*)d_in[3];
    const float* lB = (const float*)d_in[4];
    float* out = (float*)d_out;

    const int M = in_sizes[0] / D_IN;   // 8192

    // primary: small kernel, triggers completion at entry
    lora_low_kernel<<<M / 32, 256>>>(x, lA);

    // secondary: GEMM with programmatic dependent launch (overlaps kernel1)
    cudaFuncSetAttribute(gemm_lora_kernel,
                         cudaFuncAttributeMaxDynamicSharedMemorySize, SMEM_BYTES);

    cudaLaunchConfig_t cfg = {};
    cfg.gridDim  = dim3(D_OUT / BN, M / BM, 1);   // (16, 64)
    cfg.blockDim = dim3(NTHREADS, 1, 1);
    cfg.dynamicSmemBytes = SMEM_BYTES;
    cfg.stream = 0;
    cudaLaunchAttribute attrs[1];
    attrs[0].id = cudaLaunchAttributeProgrammaticStreamSerialization;
    attrs[0].val.programmaticStreamSerializationAllowed = 1;
    cfg.attrs = attrs;
    cfg.numAttrs = 1;
    cudaLaunchKernelEx(&cfg, gemm_lora_kernel, x, W, b, lB, out);
}

// round 13
// speedup vs baseline: 1.7791x; 1.0513x over previous
#include <cuda_runtime.h>
#include <cstdint>

#define D_IN   2048
#define D_OUT  2048
#define RANK   16
#define LSCALE 2.0f

#define BM  128
#define BN  128
#define BK  32
#define BKP 36            // padded row stride (floats): conflict-free, 16B-aligned
#define KT  (D_IN / BK)   // 64 main k-tiles
#define NSTAGE 3
#define NTHREADS 128

#define TILE_FLOATS (BM * BKP)
#define TILEB       (TILE_FLOATS * 4)
#define STG_FLOATS  (2 * TILE_FLOATS)
#define STG_BYTES   (STG_FLOATS * 4)
#define SMEM_BYTES  (NSTAGE * STG_BYTES)   // 110592 B x 2 CTAs = 216 KB/SM

__device__ float g_low[8192 * RANK];   // LSCALE applied at epilogue of kernel 1

// ---------------------------------------------------------------- helpers
__device__ __forceinline__ void cpasync16(uint32_t saddr, const void* gptr) {
    asm volatile("cp.async.cg.shared.global [%0], [%1], 16;" :: "r"(saddr), "l"(gptr));
}
__device__ __forceinline__ void mma_tf32(float c[4], const uint32_t a[4],
                                         const uint32_t b[2]) {
    asm volatile(
        "mma.sync.aligned.m16n8k8.row.col.f32.tf32.tf32.f32 "
        "{%0,%1,%2,%3}, {%4,%5,%6,%7}, {%8,%9}, {%0,%1,%2,%3};"
        : "+f"(c[0]), "+f"(c[1]), "+f"(c[2]), "+f"(c[3])
        : "r"(a[0]), "r"(a[1]), "r"(a[2]), "r"(a[3]), "r"(b[0]), "r"(b[1]));
}
__device__ __forceinline__ void ldsm4(uint32_t f[4], uint32_t saddr) {
    asm volatile("ldmatrix.sync.aligned.m8n8.x4.shared.b16 {%0,%1,%2,%3}, [%4];"
                 : "=r"(f[0]), "=r"(f[1]), "=r"(f[2]), "=r"(f[3]) : "r"(saddr));
}

// ---------------------------------------------------------------------------
// Kernel 1 (PDL primary, tensor-core version):
//   g_low[m, r] = LSCALE * sum_k x[m,k] * lora_A[r,k]
// 64 CTAs x 256 thr; warp w owns rows m0 + w*16 .. +15; MMA m16n8k8 tf32.
// 2-stage cp.async double buffer: x tile 128x32 + lA tile 16x32 per stage.
// ---------------------------------------------------------------------------
#define K1_XT   (BM * BKP)                  // x tile floats
#define K1_STG  ((BM + RANK) * BKP)         // + lA tile
#define K1_SMEM (2 * K1_STG * 4)            // ~41.5 KB

__global__ __launch_bounds__(256)
void lora_low_kernel(const float* __restrict__ x, const float* __restrict__ lA) {
    cudaTriggerProgrammaticLaunchCompletion();
    extern __shared__ float k1s[];

    const int tid  = threadIdx.x;
    const int lane = tid & 31;
    const int warp = tid >> 5;          // 0..7 -> rows warp*16..+15
    const int g    = lane >> 2;
    const int tg   = lane & 3;
    const int m0   = blockIdx.x * BM;

    const float* xA = x + (size_t)m0 * D_IN;
    const uint32_t sbase = (uint32_t)__cvta_generic_to_shared(k1s);

    // A x4 lane map: {m0-7,k0-3}{m8-15,k0-3}{m0-7,k4-7}{m8-15,k4-7}
    const uint32_t a_off = ((warp * 16 + (lane & 15)) * BKP + ((lane & 16) ? 4 : 0)) * 4;
    // B (lA) x4 per-ks lane map: {n0-7,k0-3}{n0-7,k4-7}{n8-15,k0-3}{n8-15,k4-7}
    const uint32_t b_off = K1_XT * 4 +
        (((lane & 7) + ((lane & 16) >> 1)) * BKP + ((lane & 8) ? 4 : 0)) * 4;

    float c[2][4];
#pragma unroll
    for (int n = 0; n < 2; n++)
#pragma unroll
        for (int q = 0; q < 4; q++) c[n][q] = 0.0f;

    // stage loader: x 128x32 (1024 float4 chunks) + lA 16x32 (128 chunks)
#define K1_LOAD(SBX, k0_)                                                      \
    do {                                                                       \
        _Pragma("unroll")                                                      \
        for (int i_ = 0; i_ < 4; i_++) {                                       \
            int idx_ = tid + i_ * 256;                                         \
            int row_ = idx_ >> 3, cg_ = idx_ & 7;                              \
            cpasync16((SBX) + (row_ * BKP + cg_ * 4) * 4,                      \
                      xA + (size_t)row_ * D_IN + (k0_) + cg_ * 4);             \
        }                                                                      \
        if (tid < 128) {                                                       \
            int row_ = tid >> 3, cg_ = tid & 7;                                \
            cpasync16((SBX) + K1_XT * 4 + (row_ * BKP + cg_ * 4) * 4,          \
                      lA + (size_t)row_ * D_IN + (k0_) + cg_ * 4);             \
        }                                                                      \
    } while (0)

    K1_LOAD(sbase, 0);
    asm volatile("cp.async.commit_group;");

#pragma unroll 1
    for (int t = 0; t < KT; t++) {
        const uint32_t SB = sbase + (t & 1) * K1_STG * 4;
        if (t + 1 < KT) {
            K1_LOAD(sbase + ((t + 1) & 1) * K1_STG * 4, (t + 1) * BK);
            asm volatile("cp.async.commit_group;");
            asm volatile("cp.async.wait_group 1;");
        } else {
            asm volatile("cp.async.wait_group 0;");
        }
        __syncthreads();

        uint32_t af[4][4], bf[4][4];
#pragma unroll
        for (int ks = 0; ks < 4; ks++) {
            ldsm4(af[ks], SB + a_off + ks * 8 * 4);
            ldsm4(bf[ks], SB + b_off + ks * 8 * 4);
        }
#pragma unroll
        for (int ks = 0; ks < 4; ks++) {
            mma_tf32(c[0], af[ks], &bf[ks][0]);   // n 0-7
            mma_tf32(c[1], af[ks], &bf[ks][2]);   // n 8-15
        }
        __syncthreads();   // frags in regs; buffer reusable next iter
    }

    // epilogue: row = m0 + warp*16 + g (+8), col = n*8 + 2*tg
#pragma unroll
    for (int n = 0; n < 2; n++) {
        int row = m0 + warp * 16 + g;
        int col = n * 8 + 2 * tg;
        *reinterpret_cast<float2*>(g_low + (size_t)row * RANK + col) =
            make_float2(c[n][0] * LSCALE, c[n][1] * LSCALE);
        *reinterpret_cast<float2*>(g_low + (size_t)(row + 8) * RANK + col) =
            make_float2(c[n][2] * LSCALE, c[n][3] * LSCALE);
    }
}

// ---------------------------------------------------------------------------
// Kernel 2 (PDL secondary): 128x128 tile, 4 warps, 64x64 warp tiles,
// ldmatrix x4 A+B, k-pipeline across barrier, triple-unrolled buffers.
// ---------------------------------------------------------------------------
__device__ __forceinline__ void load_tile_full(float* stage,
                                               const float* __restrict__ xA,
                                               const float* __restrict__ wB,
                                               int k0, int tid) {
    uint32_t sa = (uint32_t)__cvta_generic_to_shared(stage);
    uint32_t sb = sa + TILEB;
#pragma unroll
    for (int i = 0; i < 8; i++) {
        int idx = tid + i * NTHREADS;   // 0..1023
        int row = idx >> 3;
        int cg  = idx & 7;
        cpasync16(sa + (row * BKP + cg * 4) * 4, xA + (size_t)row * D_IN + k0 + cg * 4);
        cpasync16(sb + (row * BKP + cg * 4) * 4, wB + (size_t)row * D_IN + k0 + cg * 4);
    }
}

__global__ __launch_bounds__(NTHREADS, 2)
void gemm_lora_kernel(const float* __restrict__ x, const float* __restrict__ W,
                      const float* __restrict__ bias,
                      const float* __restrict__ lB,
                      float* __restrict__ out) {
    extern __shared__ float smem[];

    const int tid  = threadIdx.x;
    const int lane = tid & 31;
    const int warp = tid >> 5;     // 0..3
    const int wm   = warp >> 1;    // 0..1
    const int wn   = warp & 1;     // 0..1
    const int g    = lane >> 2;
    const int tg   = lane & 3;
    const int m0   = blockIdx.y * BM;
    const int n0   = blockIdx.x * BN;

    const float* xA = x + (size_t)m0 * D_IN;
    const float* wB = W + (size_t)n0 * D_IN;

    const uint32_t sbase = (uint32_t)__cvta_generic_to_shared(smem);
    const uint32_t a_off = ((wm * 64 + (lane & 15)) * BKP + ((lane & 16) ? 4 : 0)) * 4;
    const uint32_t b_off = TILEB +
        ((wn * 64 + ((lane & 16) >> 1) + (lane & 7)) * BKP + ((lane & 8) ? 4 : 0)) * 4;

    float c[4][8][4];
#pragma unroll
    for (int i = 0; i < 4; i++)
#pragma unroll
        for (int j = 0; j < 8; j++)
#pragma unroll
            for (int q = 0; q < 4; q++) c[i][j][q] = 0.0f;

    uint32_t afr[2][4][4];
    uint32_t bfr[2][8][2];

#define LOAD_FRAGS(pb, SBX, ks_)                                                \
    do {                                                                        \
        _Pragma("unroll")                                                       \
        for (int i_ = 0; i_ < 4; i_++)                                          \
            ldsm4(afr[pb][i_], (SBX) + a_off + (i_ * 16 * BKP + (ks_) * 8) * 4);\
        _Pragma("unroll")                                                       \
        for (int jp_ = 0; jp_ < 4; jp_++)                                       \
            ldsm4(&bfr[pb][jp_ * 2][0],                                         \
                  (SBX) + b_off + (jp_ * 16 * BKP + (ks_) * 8) * 4);            \
    } while (0)

#define MMA_ALL(cb)                                                             \
    do {                                                                        \
        _Pragma("unroll")                                                       \
        for (int i_ = 0; i_ < 4; i_++)                                          \
            _Pragma("unroll")                                                   \
            for (int j_ = 0; j_ < 8; j_++)                                      \
                mma_tf32(c[i_][j_], afr[cb][i_], bfr[cb][j_]);                  \
    } while (0)

#define LOAD_PART(PBX, tn_, p_)                                                 \
    do {                                                                        \
        if ((tn_) < KT) {                                                       \
            const int k0_ = (tn_) * BK;                                         \
            _Pragma("unroll")                                                   \
            for (int q_ = 0; q_ < 2; q_++) {                                    \
                int idx_ = tid + ((p_) * 2 + q_) * NTHREADS;  /* 0..1023 */     \
                int row_ = idx_ >> 3, cg_ = idx_ & 7;                           \
                cpasync16((PBX) + (row_ * BKP + cg_ * 4) * 4,                   \
                          xA + (size_t)row_ * D_IN + k0_ + cg_ * 4);            \
                cpasync16((PBX) + TILEB + (row_ * BKP + cg_ * 4) * 4,           \
                          wB + (size_t)row_ * D_IN + k0_ + cg_ * 4);            \
            }                                                                   \
        } else if ((tn_) == KT) {                                               \
            int idx_ = tid + (p_) * NTHREADS;                 /* 0..511 */      \
            int row_ = idx_ >> 2, cg_ = idx_ & 3;                               \
            cpasync16((PBX) + (row_ * BKP + cg_ * 4) * 4,                       \
                      g_low + (size_t)(m0 + row_) * RANK + cg_ * 4);            \
            cpasync16((PBX) + TILEB + (row_ * BKP + cg_ * 4) * 4,               \
                      lB + (size_t)(n0 + row_) * RANK + cg_ * 4);               \
        }                                                                       \
    } while (0)

#define TILE_BODY(BUFC)                                                         \
    do {                                                                        \
        const uint32_t SB = sbase + (BUFC) * STG_BYTES;                         \
        const uint32_t NB = sbase + (((BUFC) + 1) % NSTAGE) * STG_BYTES;        \
        const uint32_t PB = sbase + (((BUFC) + 2) % NSTAGE) * STG_BYTES;        \
        const int tn = t + 2;                                                   \
        LOAD_PART(PB, tn, 0);                                                   \
        LOAD_FRAGS(1, SB, 1);                                                   \
        MMA_ALL(0);                                                             \
        LOAD_PART(PB, tn, 1);                                                   \
        LOAD_FRAGS(0, SB, 2);                                                   \
        MMA_ALL(1);                                                             \
        LOAD_PART(PB, tn, 2);                                                   \
        LOAD_FRAGS(1, SB, 3);                                                   \
        MMA_ALL(0);                                                             \
        LOAD_PART(PB, tn, 3);                                                   \
        asm volatile("cp.async.commit_group;");                                 \
        asm volatile("cp.async.wait_group 1;");                                 \
        __syncthreads();                                                        \
        LOAD_FRAGS(0, NB, 0);                                                   \
        MMA_ALL(1);                                                             \
        t++;                                                                    \
    } while (0)

    // prologue: tiles 0 and 1 fully in flight
    load_tile_full(smem + 0 * STG_FLOATS, xA, wB, 0, tid);
    asm volatile("cp.async.commit_group;");
    load_tile_full(smem + 1 * STG_FLOATS, xA, wB, BK, tid);
    asm volatile("cp.async.commit_group;");

    asm volatile("cp.async.wait_group 1;");   // tile 0 resident
    __syncthreads();
    LOAD_FRAGS(0, sbase, 0);                  // (tile 0, ks 0)

    int t = 0;
#pragma unroll 1
    for (int it = 0; it < 20; it++) {         // t = 0..59
        TILE_BODY(0);
        TILE_BODY(1);
        TILE_BODY(2);
    }
    TILE_BODY(0);                             // t = 60
    TILE_BODY(1);                             // t = 61

    // kernel1's g_low must be complete before t=62 prefetches the LoRA tile
    cudaGridDependencySynchronize();

    TILE_BODY(2);                             // t = 62 (loads g_low / lB tile)
    TILE_BODY(0);                             // t = 63

    // LoRA tile (buffer 1): frags[0] already hold ks0
    {
        const uint32_t SB = sbase + 1 * STG_BYTES;
        LOAD_FRAGS(1, SB, 1);
        MMA_ALL(0);
        MMA_ALL(1);
    }

    // epilogue: add bias, store float2 pairs
#pragma unroll
    for (int i = 0; i < 4; i++) {
        int m = m0 + wm * 64 + i * 16 + g;
        float* orow0 = out + (size_t)m * D_OUT;
        float* orow1 = orow0 + (size_t)8 * D_OUT;
#pragma unroll
        for (int j = 0; j < 8; j++) {
            int n = n0 + wn * 64 + j * 8 + 2 * tg;
            float b0 = bias[n];
            float b1 = bias[n + 1];
            *reinterpret_cast<float2*>(orow0 + n) =
                make_float2(c[i][j][0] + b0, c[i][j][1] + b1);
            *reinterpret_cast<float2*>(orow1 + n) =
                make_float2(c[i][j][2] + b0, c[i][j][3] + b1);
        }
    }
}

// ---------------------------------------------------------------------------
extern "C" void kernel_launch(void* const* d_in, const int* in_sizes, int n_in,
                              void* d_out, int out_size) {
    const float* x  = (const float*)d_in[0];
    const float* W  = (const float*)d_in[1];
    const float* b  = (const float*)d_in[2];
    const float* lA = (const float*)d_in[3];
    const float* lB = (const float*)d_in[4];
    float* out = (float*)d_out;

    const int M = in_sizes[0] / D_IN;   // 8192

    // primary: tensor-core low-rank projection, single wave (64 CTAs)
    cudaFuncSetAttribute(lora_low_kernel,
                         cudaFuncAttributeMaxDynamicSharedMemorySize, K1_SMEM);
    lora_low_kernel<<<M / BM, 256, K1_SMEM>>>(x, lA);

    // secondary: GEMM with programmatic dependent launch (overlaps kernel1)
    cudaFuncSetAttribute(gemm_lora_kernel,
                         cudaFuncAttributeMaxDynamicSharedMemorySize, SMEM_BYTES);

    cudaLaunchConfig_t cfg = {};
    cfg.gridDim  = dim3(D_OUT / BN, M / BM, 1);   // (16, 64)
    cfg.blockDim = dim3(NTHREADS, 1, 1);
    cfg.dynamicSmemBytes = SMEM_BYTES;
    cfg.stream = 0;
    cudaLaunchAttribute attrs[1];
    attrs[0].id = cudaLaunchAttributeProgrammaticStreamSerialization;
    attrs[0].val.programmaticStreamSerializationAllowed = 1;
    cfg.attrs = attrs;
    cfg.numAttrs = 1;
    cudaLaunchKernelEx(&cfg, gemm_lora_kernel, x, W, b, lB, out);
}